// round 3
// baseline (speedup 1.0000x reference)
#include <cuda_runtime.h>
#include <math.h>

#define E_DIM 1024
#define S_DIM 2048
#define B_DIM 2
#define H_DIM 16
#define NROWS (B_DIM * S_DIM)   // 4096

// ---------------- scratch (no allocations allowed) ----------------
__device__ float g_h  [(size_t)NROWS * E_DIM];        // LN output (reused twice)
__device__ float g_qkv[(size_t)NROWS * 3 * E_DIM];    // QKV
__device__ float g_o  [(size_t)NROWS * E_DIM];        // attention output
__device__ float g_x2 [(size_t)NROWS * E_DIM];        // residual 1
__device__ float g_m  [(size_t)NROWS * 4 * E_DIM];    // FFN mid

// ---------------- LayerNorm: one block per row ----------------
__global__ __launch_bounds__(256) void ln_kernel(const float* __restrict__ x,
                                                 float* __restrict__ y)
{
    int row = blockIdx.x;
    int tid = threadIdx.x;
    const float* xr = x + (size_t)row * E_DIM;

    float4 v = *(const float4*)(xr + tid * 4);
    float s  = v.x + v.y + v.z + v.w;
    float ss = v.x*v.x + v.y*v.y + v.z*v.z + v.w*v.w;

    #pragma unroll
    for (int off = 16; off > 0; off >>= 1) {
        s  += __shfl_xor_sync(0xffffffffu, s,  off);
        ss += __shfl_xor_sync(0xffffffffu, ss, off);
    }

    __shared__ float rs[8], rss[8], stat[2];
    int wid = tid >> 5, lane = tid & 31;
    if (lane == 0) { rs[wid] = s; rss[wid] = ss; }
    __syncthreads();
    if (tid == 0) {
        float t = 0.f, tt = 0.f;
        #pragma unroll
        for (int i = 0; i < 8; i++) { t += rs[i]; tt += rss[i]; }
        float mean = t * (1.0f / E_DIM);
        float var  = tt * (1.0f / E_DIM) - mean * mean;
        stat[0] = mean;
        stat[1] = rsqrtf(var + 1e-5f);
    }
    __syncthreads();
    float mean = stat[0], rstd = stat[1];
    float4 o;
    o.x = (v.x - mean) * rstd;
    o.y = (v.y - mean) * rstd;
    o.z = (v.z - mean) * rstd;
    o.w = (v.w - mean) * rstd;
    *(float4*)(y + (size_t)row * E_DIM + tid * 4) = o;
}

// ---------------- SGEMM: C[M,N] = A[M,K] @ B[N,K]^T (+bias)(+relu)(+res) ----
// BM=BN=128, BK=16, 256 threads, 8x8 per thread.
#define F_BIAS 1
#define F_RELU 2
#define F_RES  4

template<int FLAGS>
__global__ __launch_bounds__(256) void sgemm_kernel(
    const float* __restrict__ A, const float* __restrict__ B,
    const float* __restrict__ bias, const float* __restrict__ res,
    float* __restrict__ C, int M, int N, int K)
{
    __shared__ float As[16 * 128];
    __shared__ float Bs[16 * 128];

    int tid = threadIdx.x;
    int tx = tid & 15, ty = tid >> 4;
    int bn = blockIdx.x, bm = blockIdx.y;

    const float* Ab = A + (size_t)bm * 128 * K;
    const float* Bb = B + (size_t)bn * 128 * K;

    float acc[8][8];
    #pragma unroll
    for (int i = 0; i < 8; i++)
        #pragma unroll
        for (int j = 0; j < 8; j++) acc[i][j] = 0.f;

    for (int k0 = 0; k0 < K; k0 += 16) {
        #pragma unroll
        for (int p = 0; p < 2; p++) {
            int idx = p * 256 + tid;
            int r = idx >> 2, c4 = idx & 3;
            float4 av = *(const float4*)(Ab + (size_t)r * K + k0 + c4 * 4);
            As[(c4*4+0)*128 + r] = av.x;
            As[(c4*4+1)*128 + r] = av.y;
            As[(c4*4+2)*128 + r] = av.z;
            As[(c4*4+3)*128 + r] = av.w;
            float4 bv = *(const float4*)(Bb + (size_t)r * K + k0 + c4 * 4);
            Bs[(c4*4+0)*128 + r] = bv.x;
            Bs[(c4*4+1)*128 + r] = bv.y;
            Bs[(c4*4+2)*128 + r] = bv.z;
            Bs[(c4*4+3)*128 + r] = bv.w;
        }
        __syncthreads();

        #pragma unroll
        for (int k = 0; k < 16; k++) {
            float4 a0 = *(const float4*)&As[k*128 + ty*8];
            float4 a1 = *(const float4*)&As[k*128 + ty*8 + 4];
            float4 b0 = *(const float4*)&Bs[k*128 + tx*8];
            float4 b1 = *(const float4*)&Bs[k*128 + tx*8 + 4];
            float ar[8] = {a0.x,a0.y,a0.z,a0.w,a1.x,a1.y,a1.z,a1.w};
            float br[8] = {b0.x,b0.y,b0.z,b0.w,b1.x,b1.y,b1.z,b1.w};
            #pragma unroll
            for (int i = 0; i < 8; i++)
                #pragma unroll
                for (int j = 0; j < 8; j++)
                    acc[i][j] += ar[i] * br[j];
        }
        __syncthreads();
    }

    // epilogue
    int col0 = bn * 128 + tx * 8;
    #pragma unroll
    for (int i = 0; i < 8; i++) {
        int row = bm * 128 + ty * 8 + i;
        #pragma unroll
        for (int j4 = 0; j4 < 2; j4++) {
            float4 v = make_float4(acc[i][j4*4+0], acc[i][j4*4+1],
                                   acc[i][j4*4+2], acc[i][j4*4+3]);
            int col = col0 + j4 * 4;
            if (FLAGS & F_BIAS) {
                float4 bb = *(const float4*)(bias + col);
                v.x += bb.x; v.y += bb.y; v.z += bb.z; v.w += bb.w;
            }
            if (FLAGS & F_RES) {
                float4 rr = *(const float4*)(res + (size_t)row * N + col);
                v.x += rr.x; v.y += rr.y; v.z += rr.z; v.w += rr.w;
            }
            if (FLAGS & F_RELU) {
                v.x = fmaxf(v.x, 0.f); v.y = fmaxf(v.y, 0.f);
                v.z = fmaxf(v.z, 0.f); v.w = fmaxf(v.w, 0.f);
            }
            *(float4*)(C + (size_t)row * N + col) = v;
        }
    }
}

// ---------------- Flash attention (fp32, causal) ----------------
// Q/K/V tiles 64x64, D=64. grid (S/64, B*H), 256 threads.
// smem: Qs[64][64], Ks[64][65] (K then reused for V), Ss[64][64], stats 192.
#define FLASH_SMEM_FLOATS (64*64 + 64*65 + 64*64 + 192)
#define FLASH_SMEM_BYTES  (FLASH_SMEM_FLOATS * 4)

__global__ __launch_bounds__(256) void flash_kernel(const float* __restrict__ qkv,
                                                    float* __restrict__ o)
{
    extern __shared__ float sm[];
    float* Qs = sm;                    // 64*64
    float* Ks = sm + 4096;             // 64*65 (K, then V)
    float* Ss = sm + 4096 + 4160;      // 64*64
    float* rowm   = Ss + 4096;         // 64
    float* rowl   = rowm + 64;         // 64
    float* ralpha = rowl + 64;         // 64

    int tid = threadIdx.x;
    int tx = tid & 15, ty = tid >> 4;
    int wid = tid >> 5, lane = tid & 31;
    int qi = blockIdx.x;
    int bh = blockIdx.y;
    int b = bh >> 4, h = bh & 15;

    const float* qbase = qkv + (size_t)b * S_DIM * (3*E_DIM) + h * 64;
    const float* kbase = qbase + E_DIM;
    const float* vbase = qbase + 2 * E_DIM;

    // load Q tile, pre-scaled by 1/sqrt(D)
    #pragma unroll
    for (int p = 0; p < 4; p++) {
        int idx = p * 256 + tid;
        int r = idx >> 4, c4 = idx & 15;
        float4 v = *(const float4*)(qbase + (size_t)(qi*64 + r) * (3*E_DIM) + c4*4);
        v.x *= 0.125f; v.y *= 0.125f; v.z *= 0.125f; v.w *= 0.125f;
        *(float4*)(Qs + r*64 + c4*4) = v;
    }
    if (tid < 64) { rowm[tid] = -1e30f; rowl[tid] = 0.f; }

    float acc[4][4];
    #pragma unroll
    for (int i = 0; i < 4; i++)
        #pragma unroll
        for (int j = 0; j < 4; j++) acc[i][j] = 0.f;

    for (int jt = 0; jt <= qi; jt++) {
        __syncthreads();   // previous PV done reading Ks/Ss; Q load done (first iter)

        // load K tile -> Ks[n][d], pad 65
        #pragma unroll
        for (int p = 0; p < 4; p++) {
            int idx = p * 256 + tid;
            int r = idx >> 4, c4 = idx & 15;
            float4 v = *(const float4*)(kbase + (size_t)(jt*64 + r) * (3*E_DIM) + c4*4);
            Ks[r*65 + c4*4 + 0] = v.x;
            Ks[r*65 + c4*4 + 1] = v.y;
            Ks[r*65 + c4*4 + 2] = v.z;
            Ks[r*65 + c4*4 + 3] = v.w;
        }
        __syncthreads();

        // scores s[4][4]: rows ty*4+i, cols tx*4+j
        float s[4][4];
        #pragma unroll
        for (int i = 0; i < 4; i++)
            #pragma unroll
            for (int j = 0; j < 4; j++) s[i][j] = 0.f;
        #pragma unroll 4
        for (int d = 0; d < 64; d++) {
            float a[4], bb[4];
            #pragma unroll
            for (int i = 0; i < 4; i++) a[i]  = Qs[(ty*4+i)*64 + d];
            #pragma unroll
            for (int j = 0; j < 4; j++) bb[j] = Ks[(tx*4+j)*65 + d];
            #pragma unroll
            for (int i = 0; i < 4; i++)
                #pragma unroll
                for (int j = 0; j < 4; j++)
                    s[i][j] += a[i] * bb[j];
        }
        if (jt == qi) {   // causal mask inside diagonal tile
            #pragma unroll
            for (int i = 0; i < 4; i++)
                #pragma unroll
                for (int j = 0; j < 4; j++)
                    if (tx*4 + j > ty*4 + i) s[i][j] = -1e30f;
        }
        __syncthreads();  // everyone done reading Ks (K); safe to overwrite with V

        // write scores, load V tile into Ks
        #pragma unroll
        for (int i = 0; i < 4; i++)
            #pragma unroll
            for (int j = 0; j < 4; j++)
                Ss[(ty*4+i)*64 + tx*4 + j] = s[i][j];
        #pragma unroll
        for (int p = 0; p < 4; p++) {
            int idx = p * 256 + tid;
            int r = idx >> 4, c4 = idx & 15;
            float4 v = *(const float4*)(vbase + (size_t)(jt*64 + r) * (3*E_DIM) + c4*4);
            Ks[r*65 + c4*4 + 0] = v.x;
            Ks[r*65 + c4*4 + 1] = v.y;
            Ks[r*65 + c4*4 + 2] = v.z;
            Ks[r*65 + c4*4 + 3] = v.w;
        }
        __syncthreads();

        // online softmax: one warp per row, 8 rows per pass
        for (int r = wid; r < 64; r += 8) {
            float v0 = Ss[r*64 + lane];
            float v1 = Ss[r*64 + 32 + lane];
            float mx = fmaxf(v0, v1);
            #pragma unroll
            for (int off = 16; off > 0; off >>= 1)
                mx = fmaxf(mx, __shfl_xor_sync(0xffffffffu, mx, off));
            float mo = rowm[r];
            float mn = fmaxf(mo, mx);
            float e0 = __expf(v0 - mn);
            float e1 = __expf(v1 - mn);
            float sum = e0 + e1;
            #pragma unroll
            for (int off = 16; off > 0; off >>= 1)
                sum += __shfl_xor_sync(0xffffffffu, sum, off);
            if (lane == 0) {
                float al = __expf(mo - mn);
                ralpha[r] = al;
                rowl[r] = rowl[r] * al + sum;
                rowm[r] = mn;
            }
            Ss[r*64 + lane]      = e0;
            Ss[r*64 + 32 + lane] = e1;
        }
        __syncthreads();

        // rescale accumulators, then O += P @ V
        #pragma unroll
        for (int i = 0; i < 4; i++) {
            float al = ralpha[ty*4 + i];
            #pragma unroll
            for (int j = 0; j < 4; j++) acc[i][j] *= al;
        }
        #pragma unroll 4
        for (int kc = 0; kc < 64; kc++) {
            float p[4], vv[4];
            #pragma unroll
            for (int i = 0; i < 4; i++) p[i]  = Ss[(ty*4+i)*64 + kc];
            #pragma unroll
            for (int j = 0; j < 4; j++) vv[j] = Ks[kc*65 + tx*4 + j];
            #pragma unroll
            for (int i = 0; i < 4; i++)
                #pragma unroll
                for (int j = 0; j < 4; j++)
                    acc[i][j] += p[i] * vv[j];
        }
    }

    // finalize: divide by l, write O at [b, qi*64+row, h*64+col]
    float* ob = o + (size_t)b * S_DIM * E_DIM + h * 64;
    #pragma unroll
    for (int i = 0; i < 4; i++) {
        float inv = 1.0f / rowl[ty*4 + i];
        float4 v = make_float4(acc[i][0]*inv, acc[i][1]*inv,
                               acc[i][2]*inv, acc[i][3]*inv);
        *(float4*)(ob + (size_t)(qi*64 + ty*4 + i) * E_DIM + tx*4) = v;
    }
}

// ---------------- launch ----------------
extern "C" void kernel_launch(void* const* d_in, const int* in_sizes, int n_in,
                              void* d_out, int out_size)
{
    const float* x      = (const float*)d_in[0];
    const float* w_in   = (const float*)d_in[1];
    const float* w_out  = (const float*)d_in[2];
    const float* w_fc   = (const float*)d_in[3];
    const float* b_fc   = (const float*)d_in[4];
    const float* w_proj = (const float*)d_in[5];
    const float* b_proj = (const float*)d_in[6];
    float* out = (float*)d_out;

    void *ph, *pqkv, *po, *px2, *pm;
    cudaGetSymbolAddress(&ph,   g_h);
    cudaGetSymbolAddress(&pqkv, g_qkv);
    cudaGetSymbolAddress(&po,   g_o);
    cudaGetSymbolAddress(&px2,  g_x2);
    cudaGetSymbolAddress(&pm,   g_m);
    float* bh   = (float*)ph;
    float* bqkv = (float*)pqkv;
    float* bo   = (float*)po;
    float* bx2  = (float*)px2;
    float* bm   = (float*)pm;

    cudaFuncSetAttribute(flash_kernel,
                         cudaFuncAttributeMaxDynamicSharedMemorySize,
                         FLASH_SMEM_BYTES);

    // 1) h = LN(x)
    ln_kernel<<<NROWS, 256>>>(x, bh);
    // 2) qkv = h @ w_in^T         [4096, 3072]
    sgemm_kernel<0><<<dim3(3072/128, NROWS/128), 256>>>(
        bh, w_in, nullptr, nullptr, bqkv, NROWS, 3072, 1024);
    // 3) o = causal attention(qkv)
    flash_kernel<<<dim3(S_DIM/64, B_DIM*H_DIM), 256, FLASH_SMEM_BYTES>>>(bqkv, bo);
    // 4) x2 = o @ w_out^T + x
    sgemm_kernel<F_RES><<<dim3(1024/128, NROWS/128), 256>>>(
        bo, w_out, nullptr, x, bx2, NROWS, 1024, 1024);
    // 5) h = LN(x2)
    ln_kernel<<<NROWS, 256>>>(bx2, bh);
    // 6) m = relu(h @ w_fc^T + b_fc)   [4096, 4096]
    sgemm_kernel<F_BIAS|F_RELU><<<dim3(4096/128, NROWS/128), 256>>>(
        bh, w_fc, b_fc, nullptr, bm, NROWS, 4096, 1024);
    // 7) out = m @ w_proj^T + b_proj + x2
    sgemm_kernel<F_BIAS|F_RES><<<dim3(1024/128, NROWS/128), 256>>>(
        bm, w_proj, b_proj, bx2, out, NROWS, 1024, 4096);
}

// round 9
// speedup vs baseline: 1.6140x; 1.6140x over previous
#include <cuda_runtime.h>
#include <cuda_bf16.h>
#include <math.h>
#include <stdint.h>

#define E_DIM 1024
#define S_DIM 2048
#define B_DIM 2
#define H_DIM 16
#define NROWS (B_DIM * S_DIM)   // 4096

// ---------------- scratch (no allocations allowed) ----------------
__device__ float g_h  [(size_t)NROWS * E_DIM];
__device__ float g_qkv[(size_t)NROWS * 3 * E_DIM];
__device__ float g_o  [(size_t)NROWS * E_DIM];
__device__ float g_x2 [(size_t)NROWS * E_DIM];
__device__ float g_m  [(size_t)NROWS * 4 * E_DIM];

// ================= helpers =================
__device__ __forceinline__ uint32_t smem_u32(const void* p) {
    uint32_t a;
    asm("{ .reg .u64 t; cvta.to.shared.u64 t, %1; cvt.u32.u64 %0, t; }"
        : "=r"(a) : "l"(p));
    return a;
}

__device__ __forceinline__ void ldsm4(uint32_t* r, uint32_t addr) {
    asm volatile("ldmatrix.sync.aligned.m8n8.x4.shared.b16 {%0,%1,%2,%3}, [%4];"
        : "=r"(r[0]), "=r"(r[1]), "=r"(r[2]), "=r"(r[3]) : "r"(addr));
}

__device__ __forceinline__ void mma16816(float* d, const uint32_t* a, const uint32_t* b) {
    asm volatile(
        "mma.sync.aligned.m16n8k16.row.col.f32.bf16.bf16.f32 "
        "{%0,%1,%2,%3}, {%4,%5,%6,%7}, {%8,%9}, {%0,%1,%2,%3};"
        : "+f"(d[0]), "+f"(d[1]), "+f"(d[2]), "+f"(d[3])
        : "r"(a[0]), "r"(a[1]), "r"(a[2]), "r"(a[3]), "r"(b[0]), "r"(b[1]));
}

#define STS128A(addr, v) \
    asm volatile("st.shared.v4.b32 [%0], {%1, %2, %3, %4};" \
        :: "r"(addr), "r"((v).x), "r"((v).y), "r"((v).z), "r"((v).w) : "memory")

__device__ __forceinline__ void cvt8(float4 v0, float4 v1, uint4& hi, uint4& lo) {
    float x[8] = {v0.x, v0.y, v0.z, v0.w, v1.x, v1.y, v1.z, v1.w};
    uint32_t h[4], l[4];
    #pragma unroll
    for (int i = 0; i < 4; i++) {
        __nv_bfloat16 a = __float2bfloat16_rn(x[2*i]);
        __nv_bfloat16 b = __float2bfloat16_rn(x[2*i+1]);
        __nv_bfloat16 c = __float2bfloat16_rn(x[2*i]   - __bfloat162float(a));
        __nv_bfloat16 d = __float2bfloat16_rn(x[2*i+1] - __bfloat162float(b));
        h[i] = (uint32_t)__bfloat16_as_ushort(a) | ((uint32_t)__bfloat16_as_ushort(b) << 16);
        l[i] = (uint32_t)__bfloat16_as_ushort(c) | ((uint32_t)__bfloat16_as_ushort(d) << 16);
    }
    hi = make_uint4(h[0], h[1], h[2], h[3]);
    lo = make_uint4(l[0], l[1], l[2], l[3]);
}

// ---------------- LayerNorm ----------------
__global__ __launch_bounds__(256) void ln_kernel(const float* __restrict__ x,
                                                 float* __restrict__ y)
{
    int row = blockIdx.x;
    int tid = threadIdx.x;
    const float* xr = x + (size_t)row * E_DIM;

    float4 v = *(const float4*)(xr + tid * 4);
    float s  = v.x + v.y + v.z + v.w;
    float ss = v.x*v.x + v.y*v.y + v.z*v.z + v.w*v.w;

    #pragma unroll
    for (int off = 16; off > 0; off >>= 1) {
        s  += __shfl_xor_sync(0xffffffffu, s,  off);
        ss += __shfl_xor_sync(0xffffffffu, ss, off);
    }

    __shared__ float rs[8], rss[8], stat[2];
    int wid = tid >> 5, lane = tid & 31;
    if (lane == 0) { rs[wid] = s; rss[wid] = ss; }
    __syncthreads();
    if (tid == 0) {
        float t = 0.f, tt = 0.f;
        #pragma unroll
        for (int i = 0; i < 8; i++) { t += rs[i]; tt += rss[i]; }
        float mean = t * (1.0f / E_DIM);
        float var  = tt * (1.0f / E_DIM) - mean * mean;
        stat[0] = mean;
        stat[1] = rsqrtf(var + 1e-5f);
    }
    __syncthreads();
    float mean = stat[0], rstd = stat[1];
    float4 o;
    o.x = (v.x - mean) * rstd;
    o.y = (v.y - mean) * rstd;
    o.z = (v.z - mean) * rstd;
    o.w = (v.w - mean) * rstd;
    *(float4*)(y + (size_t)row * E_DIM + tid * 4) = o;
}

// ================= mma.sync bf16x3 GEMM =================
// C[M,N] = A[M,K] @ B[N,K]^T, fp32 via bf16 hi/lo split (3 products).
// Tile 128x128, BK=32, 256 threads (8 warps, warp tile 32x64), 2-stage smem.
#define F_BIAS 1
#define F_RELU 2
#define F_RES  4

// smem per stage: 4 tiles (Ahi, Alo, Bhi, Blo), each 128 rows x 40 bf16 (80B)
#define GM_TILE  10240
#define GM_STAGE (4 * GM_TILE)      // 40960
#define GM_SMEM  (2 * GM_STAGE)     // 81920

template<int FLAGS>
__global__ __launch_bounds__(256, 1)
void gemm_mma_kernel(const float* __restrict__ A, const float* __restrict__ B,
                     const float* __restrict__ bias, const float* __restrict__ res,
                     float* __restrict__ C, int M, int N, int K)
{
    extern __shared__ __align__(16) char smem[];
    uint32_t sb = smem_u32(smem);

    int tid = threadIdx.x;
    int lane = tid & 31, wid = tid >> 5;
    int wm = wid >> 1, wn = wid & 1;          // 4 x 2 warp grid
    int bn = blockIdx.x, bm = blockIdx.y;

    const float* Ab = A + (size_t)bm * 128 * K;
    const float* Bb = B + (size_t)bn * 128 * K;

    // global load mapping: row = tid>>1 (0..127), 16 floats starting at c16
    int r = tid >> 1;
    int c16 = (tid & 1) * 16;
    uint32_t sts_off = (uint32_t)(r * 80 + c16 * 2);

    // ldmatrix per-thread offsets
    uint32_t rpA = (uint32_t)((wm * 32 + (lane & 15)) * 80 + (lane >> 4) * 16);
    int g = lane >> 3, l8 = lane & 7;
    uint32_t rpB = (uint32_t)((wn * 64 + l8 + (g >> 1) * 8) * 80 + (g & 1) * 16);

    float acc[2][8][4];
    #pragma unroll
    for (int mt = 0; mt < 2; mt++)
        #pragma unroll
        for (int nt = 0; nt < 8; nt++)
            #pragma unroll
            for (int i = 0; i < 4; i++) acc[mt][nt][i] = 0.f;

    int nch = K >> 5;
    float4 av[4], bv[4];

    // prologue: load + store chunk 0
    {
        const float* ap = Ab + (size_t)r * K + c16;
        const float* bp = Bb + (size_t)r * K + c16;
        #pragma unroll
        for (int i = 0; i < 4; i++) { av[i] = *(const float4*)(ap + i*4);
                                      bv[i] = *(const float4*)(bp + i*4); }
        uint4 h0, l0, h1, l1;
        cvt8(av[0], av[1], h0, l0); cvt8(av[2], av[3], h1, l1);
        STS128A(sb + 0*GM_TILE + sts_off,      h0);
        STS128A(sb + 0*GM_TILE + sts_off + 16, h1);
        STS128A(sb + 1*GM_TILE + sts_off,      l0);
        STS128A(sb + 1*GM_TILE + sts_off + 16, l1);
        cvt8(bv[0], bv[1], h0, l0); cvt8(bv[2], bv[3], h1, l1);
        STS128A(sb + 2*GM_TILE + sts_off,      h0);
        STS128A(sb + 2*GM_TILE + sts_off + 16, h1);
        STS128A(sb + 3*GM_TILE + sts_off,      l0);
        STS128A(sb + 3*GM_TILE + sts_off + 16, l1);
    }
    __syncthreads();

    for (int kc = 0; kc < nch; kc++) {
        int s = kc & 1;
        if (kc + 1 < nch) {
            int k0 = (kc + 1) << 5;
            const float* ap = Ab + (size_t)r * K + k0 + c16;
            const float* bp = Bb + (size_t)r * K + k0 + c16;
            #pragma unroll
            for (int i = 0; i < 4; i++) { av[i] = *(const float4*)(ap + i*4);
                                          bv[i] = *(const float4*)(bp + i*4); }
        }

        uint32_t base = sb + (uint32_t)s * GM_STAGE;
        uint32_t aHi = base, aLo = base + GM_TILE;
        uint32_t bHi = base + 2*GM_TILE, bLo = base + 3*GM_TILE;

        #pragma unroll
        for (int k16 = 0; k16 < 2; k16++) {
            uint32_t ko = (uint32_t)k16 * 32;
            uint32_t ah[8], ax[8], bh[16], bx[16];

            ldsm4(ah + 0, aHi + rpA + ko);
            ldsm4(ah + 4, aHi + rpA + 1280 + ko);
            #pragma unroll
            for (int i = 0; i < 4; i++)
                ldsm4(bh + i*4, bHi + rpB + (uint32_t)i*1280 + ko);
            #pragma unroll
            for (int mt = 0; mt < 2; mt++)
                #pragma unroll
                for (int nt = 0; nt < 8; nt++)
                    mma16816(acc[mt][nt], ah + mt*4, bh + nt*2);

            ldsm4(ax + 0, aLo + rpA + ko);
            ldsm4(ax + 4, aLo + rpA + 1280 + ko);
            #pragma unroll
            for (int mt = 0; mt < 2; mt++)
                #pragma unroll
                for (int nt = 0; nt < 8; nt++)
                    mma16816(acc[mt][nt], ax + mt*4, bh + nt*2);

            #pragma unroll
            for (int i = 0; i < 4; i++)
                ldsm4(bx + i*4, bLo + rpB + (uint32_t)i*1280 + ko);
            #pragma unroll
            for (int mt = 0; mt < 2; mt++)
                #pragma unroll
                for (int nt = 0; nt < 8; nt++)
                    mma16816(acc[mt][nt], ah + mt*4, bx + nt*2);
        }

        if (kc + 1 < nch) {
            uint32_t nbase = sb + (uint32_t)(s ^ 1) * GM_STAGE;
            uint4 h0, l0, h1, l1;
            cvt8(av[0], av[1], h0, l0); cvt8(av[2], av[3], h1, l1);
            STS128A(nbase + 0*GM_TILE + sts_off,      h0);
            STS128A(nbase + 0*GM_TILE + sts_off + 16, h1);
            STS128A(nbase + 1*GM_TILE + sts_off,      l0);
            STS128A(nbase + 1*GM_TILE + sts_off + 16, l1);
            cvt8(bv[0], bv[1], h0, l0); cvt8(bv[2], bv[3], h1, l1);
            STS128A(nbase + 2*GM_TILE + sts_off,      h0);
            STS128A(nbase + 2*GM_TILE + sts_off + 16, h1);
            STS128A(nbase + 3*GM_TILE + sts_off,      l0);
            STS128A(nbase + 3*GM_TILE + sts_off + 16, l1);
        }
        __syncthreads();
    }

    // epilogue: thread (lane) holds c pairs at rows lane>>2 (+8), cols (lane&3)*2
    #pragma unroll
    for (int mt = 0; mt < 2; mt++) {
        int gr0 = bm*128 + wm*32 + mt*16 + (lane >> 2);
        #pragma unroll
        for (int nt = 0; nt < 8; nt++) {
            int gc = bn*128 + wn*64 + nt*8 + (lane & 3)*2;
            #pragma unroll
            for (int hfl = 0; hfl < 2; hfl++) {
                int row = gr0 + hfl*8;
                float v0 = acc[mt][nt][hfl*2+0];
                float v1 = acc[mt][nt][hfl*2+1];
                if (FLAGS & F_BIAS) {
                    v0 += __ldg(bias + gc);
                    v1 += __ldg(bias + gc + 1);
                }
                if (FLAGS & F_RES) {
                    float2 rr = *(const float2*)(res + (size_t)row * N + gc);
                    v0 += rr.x; v1 += rr.y;
                }
                if (FLAGS & F_RELU) { v0 = fmaxf(v0, 0.f); v1 = fmaxf(v1, 0.f); }
                float2 o = make_float2(v0, v1);
                *(float2*)(C + (size_t)row * N + gc) = o;
            }
        }
    }
}

// ---------------- Flash attention (fp32, causal) ----------------
#define FLASH_SMEM_FLOATS (64*64 + 64*65 + 64*64 + 192)
#define FLASH_SMEM_BYTES  (FLASH_SMEM_FLOATS * 4)

__global__ __launch_bounds__(256) void flash_kernel(const float* __restrict__ qkv,
                                                    float* __restrict__ o)
{
    extern __shared__ float sm[];
    float* Qs = sm;
    float* Ks = sm + 4096;
    float* Ss = sm + 4096 + 4160;
    float* rowm   = Ss + 4096;
    float* rowl   = rowm + 64;
    float* ralpha = rowl + 64;

    int tid = threadIdx.x;
    int tx = tid & 15, ty = tid >> 4;
    int wid = tid >> 5, lane = tid & 31;
    int qi = blockIdx.x;
    int bh = blockIdx.y;
    int b = bh >> 4, h = bh & 15;

    const float* qbase = qkv + (size_t)b * S_DIM * (3*E_DIM) + h * 64;
    const float* kbase = qbase + E_DIM;
    const float* vbase = qbase + 2 * E_DIM;

    #pragma unroll
    for (int p = 0; p < 4; p++) {
        int idx = p * 256 + tid;
        int r = idx >> 4, c4 = idx & 15;
        float4 v = *(const float4*)(qbase + (size_t)(qi*64 + r) * (3*E_DIM) + c4*4);
        v.x *= 0.125f; v.y *= 0.125f; v.z *= 0.125f; v.w *= 0.125f;
        *(float4*)(Qs + r*64 + c4*4) = v;
    }
    if (tid < 64) { rowm[tid] = -1e30f; rowl[tid] = 0.f; }

    float acc[4][4];
    #pragma unroll
    for (int i = 0; i < 4; i++)
        #pragma unroll
        for (int j = 0; j < 4; j++) acc[i][j] = 0.f;

    for (int jt = 0; jt <= qi; jt++) {
        __syncthreads();

        #pragma unroll
        for (int p = 0; p < 4; p++) {
            int idx = p * 256 + tid;
            int r = idx >> 4, c4 = idx & 15;
            float4 v = *(const float4*)(kbase + (size_t)(jt*64 + r) * (3*E_DIM) + c4*4);
            Ks[r*65 + c4*4 + 0] = v.x;
            Ks[r*65 + c4*4 + 1] = v.y;
            Ks[r*65 + c4*4 + 2] = v.z;
            Ks[r*65 + c4*4 + 3] = v.w;
        }
        __syncthreads();

        float s[4][4];
        #pragma unroll
        for (int i = 0; i < 4; i++)
            #pragma unroll
            for (int j = 0; j < 4; j++) s[i][j] = 0.f;
        #pragma unroll 4
        for (int d = 0; d < 64; d++) {
            float a[4], bb[4];
            #pragma unroll
            for (int i = 0; i < 4; i++) a[i]  = Qs[(ty*4+i)*64 + d];
            #pragma unroll
            for (int j = 0; j < 4; j++) bb[j] = Ks[(tx*4+j)*65 + d];
            #pragma unroll
            for (int i = 0; i < 4; i++)
                #pragma unroll
                for (int j = 0; j < 4; j++)
                    s[i][j] += a[i] * bb[j];
        }
        if (jt == qi) {
            #pragma unroll
            for (int i = 0; i < 4; i++)
                #pragma unroll
                for (int j = 0; j < 4; j++)
                    if (tx*4 + j > ty*4 + i) s[i][j] = -1e30f;
        }
        __syncthreads();

        #pragma unroll
        for (int i = 0; i < 4; i++)
            #pragma unroll
            for (int j = 0; j < 4; j++)
                Ss[(ty*4+i)*64 + tx*4 + j] = s[i][j];
        #pragma unroll
        for (int p = 0; p < 4; p++) {
            int idx = p * 256 + tid;
            int r = idx >> 4, c4 = idx & 15;
            float4 v = *(const float4*)(vbase + (size_t)(jt*64 + r) * (3*E_DIM) + c4*4);
            Ks[r*65 + c4*4 + 0] = v.x;
            Ks[r*65 + c4*4 + 1] = v.y;
            Ks[r*65 + c4*4 + 2] = v.z;
            Ks[r*65 + c4*4 + 3] = v.w;
        }
        __syncthreads();

        for (int rr = wid; rr < 64; rr += 8) {
            float v0 = Ss[rr*64 + lane];
            float v1 = Ss[rr*64 + 32 + lane];
            float mx = fmaxf(v0, v1);
            #pragma unroll
            for (int off = 16; off > 0; off >>= 1)
                mx = fmaxf(mx, __shfl_xor_sync(0xffffffffu, mx, off));
            float mo = rowm[rr];
            float mn = fmaxf(mo, mx);
            float e0 = __expf(v0 - mn);
            float e1 = __expf(v1 - mn);
            float sum = e0 + e1;
            #pragma unroll
            for (int off = 16; off > 0; off >>= 1)
                sum += __shfl_xor_sync(0xffffffffu, sum, off);
            if (lane == 0) {
                float al = __expf(mo - mn);
                ralpha[rr] = al;
                rowl[rr] = rowl[rr] * al + sum;
                rowm[rr] = mn;
            }
            Ss[rr*64 + lane]      = e0;
            Ss[rr*64 + 32 + lane] = e1;
        }
        __syncthreads();

        #pragma unroll
        for (int i = 0; i < 4; i++) {
            float al = ralpha[ty*4 + i];
            #pragma unroll
            for (int j = 0; j < 4; j++) acc[i][j] *= al;
        }
        #pragma unroll 4
        for (int kc = 0; kc < 64; kc++) {
            float p[4], vv[4];
            #pragma unroll
            for (int i = 0; i < 4; i++) p[i]  = Ss[(ty*4+i)*64 + kc];
            #pragma unroll
            for (int j = 0; j < 4; j++) vv[j] = Ks[kc*65 + tx*4 + j];
            #pragma unroll
            for (int i = 0; i < 4; i++)
                #pragma unroll
                for (int j = 0; j < 4; j++)
                    acc[i][j] += p[i] * vv[j];
        }
    }

    float* ob = o + (size_t)b * S_DIM * E_DIM + h * 64;
    #pragma unroll
    for (int i = 0; i < 4; i++) {
        float inv = 1.0f / rowl[ty*4 + i];
        float4 v = make_float4(acc[i][0]*inv, acc[i][1]*inv,
                               acc[i][2]*inv, acc[i][3]*inv);
        *(float4*)(ob + (size_t)(qi*64 + ty*4 + i) * E_DIM + tx*4) = v;
    }
}

// ---------------- launch ----------------
extern "C" void kernel_launch(void* const* d_in, const int* in_sizes, int n_in,
                              void* d_out, int out_size)
{
    const float* x      = (const float*)d_in[0];
    const float* w_in   = (const float*)d_in[1];
    const float* w_out  = (const float*)d_in[2];
    const float* w_fc   = (const float*)d_in[3];
    const float* b_fc   = (const float*)d_in[4];
    const float* w_proj = (const float*)d_in[5];
    const float* b_proj = (const float*)d_in[6];
    float* out = (float*)d_out;

    void *ph, *pqkv, *po, *px2, *pm;
    cudaGetSymbolAddress(&ph,   g_h);
    cudaGetSymbolAddress(&pqkv, g_qkv);
    cudaGetSymbolAddress(&po,   g_o);
    cudaGetSymbolAddress(&px2,  g_x2);
    cudaGetSymbolAddress(&pm,   g_m);
    float* bh   = (float*)ph;
    float* bqkv = (float*)pqkv;
    float* bo   = (float*)po;
    float* bx2  = (float*)px2;
    float* bm   = (float*)pm;

    cudaFuncSetAttribute(flash_kernel,
                         cudaFuncAttributeMaxDynamicSharedMemorySize,
                         FLASH_SMEM_BYTES);
    cudaFuncSetAttribute(gemm_mma_kernel<0>,
                         cudaFuncAttributeMaxDynamicSharedMemorySize, GM_SMEM);
    cudaFuncSetAttribute(gemm_mma_kernel<F_RES>,
                         cudaFuncAttributeMaxDynamicSharedMemorySize, GM_SMEM);
    cudaFuncSetAttribute(gemm_mma_kernel<F_BIAS|F_RELU>,
                         cudaFuncAttributeMaxDynamicSharedMemorySize, GM_SMEM);
    cudaFuncSetAttribute(gemm_mma_kernel<F_BIAS|F_RES>,
                         cudaFuncAttributeMaxDynamicSharedMemorySize, GM_SMEM);

    // 1) h = LN(x)
    ln_kernel<<<NROWS, 256>>>(x, bh);
    // 2) qkv = h @ w_in^T         [4096, 3072]
    gemm_mma_kernel<0><<<dim3(3072/128, NROWS/128), 256, GM_SMEM>>>(
        bh, w_in, nullptr, nullptr, bqkv, NROWS, 3072, 1024);
    // 3) o = causal attention(qkv)
    flash_kernel<<<dim3(S_DIM/64, B_DIM*H_DIM), 256, FLASH_SMEM_BYTES>>>(bqkv, bo);
    // 4) x2 = o @ w_out^T + x
    gemm_mma_kernel<F_RES><<<dim3(1024/128, NROWS/128), 256, GM_SMEM>>>(
        bo, w_out, nullptr, x, bx2, NROWS, 1024, 1024);
    // 5) h = LN(x2)
    ln_kernel<<<NROWS, 256>>>(bx2, bh);
    // 6) m = relu(h @ w_fc^T + b_fc)   [4096, 4096]
    gemm_mma_kernel<F_BIAS|F_RELU><<<dim3(4096/128, NROWS/128), 256, GM_SMEM>>>(
        bh, w_fc, b_fc, nullptr, bm, NROWS, 4096, 1024);
    // 7) out = m @ w_proj^T + b_proj + x2
    gemm_mma_kernel<F_BIAS|F_RES><<<dim3(1024/128, NROWS/128), 256, GM_SMEM>>>(
        bm, w_proj, b_proj, bx2, out, NROWS, 1024, 4096);
}

// round 10
// speedup vs baseline: 2.1560x; 1.3358x over previous
#include <cuda_runtime.h>
#include <cuda_bf16.h>
#include <math.h>
#include <stdint.h>

#define E_DIM 1024
#define S_DIM 2048
#define B_DIM 2
#define H_DIM 16
#define NROWS (B_DIM * S_DIM)   // 4096

// ---------------- scratch (no allocations allowed) ----------------
__device__ float g_h  [(size_t)NROWS * E_DIM];
__device__ float g_qkv[(size_t)NROWS * 3 * E_DIM];
__device__ float g_o  [(size_t)NROWS * E_DIM];
__device__ float g_x2 [(size_t)NROWS * E_DIM];
__device__ float g_m  [(size_t)NROWS * 4 * E_DIM];

// ================= helpers =================
__device__ __forceinline__ uint32_t smem_u32(const void* p) {
    uint32_t a;
    asm("{ .reg .u64 t; cvta.to.shared.u64 t, %1; cvt.u32.u64 %0, t; }"
        : "=r"(a) : "l"(p));
    return a;
}

__device__ __forceinline__ void ldsm4(uint32_t* r, uint32_t addr) {
    asm volatile("ldmatrix.sync.aligned.m8n8.x4.shared.b16 {%0,%1,%2,%3}, [%4];"
        : "=r"(r[0]), "=r"(r[1]), "=r"(r[2]), "=r"(r[3]) : "r"(addr));
}

__device__ __forceinline__ void ldsm4t(uint32_t* r, uint32_t addr) {
    asm volatile("ldmatrix.sync.aligned.m8n8.x4.trans.shared.b16 {%0,%1,%2,%3}, [%4];"
        : "=r"(r[0]), "=r"(r[1]), "=r"(r[2]), "=r"(r[3]) : "r"(addr));
}

__device__ __forceinline__ void mma16816(float* d, const uint32_t* a, const uint32_t* b) {
    asm volatile(
        "mma.sync.aligned.m16n8k16.row.col.f32.bf16.bf16.f32 "
        "{%0,%1,%2,%3}, {%4,%5,%6,%7}, {%8,%9}, {%0,%1,%2,%3};"
        : "+f"(d[0]), "+f"(d[1]), "+f"(d[2]), "+f"(d[3])
        : "r"(a[0]), "r"(a[1]), "r"(a[2]), "r"(a[3]), "r"(b[0]), "r"(b[1]));
}

#define STS128A(addr, v) \
    asm volatile("st.shared.v4.b32 [%0], {%1, %2, %3, %4};" \
        :: "r"(addr), "r"((v).x), "r"((v).y), "r"((v).z), "r"((v).w) : "memory")

__device__ __forceinline__ void cvt8(float4 v0, float4 v1, uint4& hi, uint4& lo) {
    float x[8] = {v0.x, v0.y, v0.z, v0.w, v1.x, v1.y, v1.z, v1.w};
    uint32_t h[4], l[4];
    #pragma unroll
    for (int i = 0; i < 4; i++) {
        __nv_bfloat16 a = __float2bfloat16_rn(x[2*i]);
        __nv_bfloat16 b = __float2bfloat16_rn(x[2*i+1]);
        __nv_bfloat16 c = __float2bfloat16_rn(x[2*i]   - __bfloat162float(a));
        __nv_bfloat16 d = __float2bfloat16_rn(x[2*i+1] - __bfloat162float(b));
        h[i] = (uint32_t)__bfloat16_as_ushort(a) | ((uint32_t)__bfloat16_as_ushort(b) << 16);
        l[i] = (uint32_t)__bfloat16_as_ushort(c) | ((uint32_t)__bfloat16_as_ushort(d) << 16);
    }
    hi = make_uint4(h[0], h[1], h[2], h[3]);
    lo = make_uint4(l[0], l[1], l[2], l[3]);
}

__device__ __forceinline__ void packhl(float a, float b, uint32_t& hi, uint32_t& lo) {
    __nv_bfloat16 ah = __float2bfloat16_rn(a);
    __nv_bfloat16 bh = __float2bfloat16_rn(b);
    __nv_bfloat16 al = __float2bfloat16_rn(a - __bfloat162float(ah));
    __nv_bfloat16 bl = __float2bfloat16_rn(b - __bfloat162float(bh));
    hi = (uint32_t)__bfloat16_as_ushort(ah) | ((uint32_t)__bfloat16_as_ushort(bh) << 16);
    lo = (uint32_t)__bfloat16_as_ushort(al) | ((uint32_t)__bfloat16_as_ushort(bl) << 16);
}

// ---------------- LayerNorm ----------------
__global__ __launch_bounds__(256) void ln_kernel(const float* __restrict__ x,
                                                 float* __restrict__ y)
{
    int row = blockIdx.x;
    int tid = threadIdx.x;
    const float* xr = x + (size_t)row * E_DIM;

    float4 v = *(const float4*)(xr + tid * 4);
    float s  = v.x + v.y + v.z + v.w;
    float ss = v.x*v.x + v.y*v.y + v.z*v.z + v.w*v.w;

    #pragma unroll
    for (int off = 16; off > 0; off >>= 1) {
        s  += __shfl_xor_sync(0xffffffffu, s,  off);
        ss += __shfl_xor_sync(0xffffffffu, ss, off);
    }

    __shared__ float rs[8], rss[8], stat[2];
    int wid = tid >> 5, lane = tid & 31;
    if (lane == 0) { rs[wid] = s; rss[wid] = ss; }
    __syncthreads();
    if (tid == 0) {
        float t = 0.f, tt = 0.f;
        #pragma unroll
        for (int i = 0; i < 8; i++) { t += rs[i]; tt += rss[i]; }
        float mean = t * (1.0f / E_DIM);
        float var  = tt * (1.0f / E_DIM) - mean * mean;
        stat[0] = mean;
        stat[1] = rsqrtf(var + 1e-5f);
    }
    __syncthreads();
    float mean = stat[0], rstd = stat[1];
    float4 o;
    o.x = (v.x - mean) * rstd;
    o.y = (v.y - mean) * rstd;
    o.z = (v.z - mean) * rstd;
    o.w = (v.w - mean) * rstd;
    *(float4*)(y + (size_t)row * E_DIM + tid * 4) = o;
}

// ================= mma.sync bf16x3 GEMM (unchanged from R9) =================
#define F_BIAS 1
#define F_RELU 2
#define F_RES  4

#define GM_TILE  10240
#define GM_STAGE (4 * GM_TILE)
#define GM_SMEM  (2 * GM_STAGE)

template<int FLAGS>
__global__ __launch_bounds__(256, 1)
void gemm_mma_kernel(const float* __restrict__ A, const float* __restrict__ B,
                     const float* __restrict__ bias, const float* __restrict__ res,
                     float* __restrict__ C, int M, int N, int K)
{
    extern __shared__ __align__(16) char smem[];
    uint32_t sb = smem_u32(smem);

    int tid = threadIdx.x;
    int lane = tid & 31, wid = tid >> 5;
    int wm = wid >> 1, wn = wid & 1;
    int bn = blockIdx.x, bm = blockIdx.y;

    const float* Ab = A + (size_t)bm * 128 * K;
    const float* Bb = B + (size_t)bn * 128 * K;

    int r = tid >> 1;
    int c16 = (tid & 1) * 16;
    uint32_t sts_off = (uint32_t)(r * 80 + c16 * 2);

    uint32_t rpA = (uint32_t)((wm * 32 + (lane & 15)) * 80 + (lane >> 4) * 16);
    int g = lane >> 3, l8 = lane & 7;
    uint32_t rpB = (uint32_t)((wn * 64 + l8 + (g >> 1) * 8) * 80 + (g & 1) * 16);

    float acc[2][8][4];
    #pragma unroll
    for (int mt = 0; mt < 2; mt++)
        #pragma unroll
        for (int nt = 0; nt < 8; nt++)
            #pragma unroll
            for (int i = 0; i < 4; i++) acc[mt][nt][i] = 0.f;

    int nch = K >> 5;
    float4 av[4], bv[4];

    {
        const float* ap = Ab + (size_t)r * K + c16;
        const float* bp = Bb + (size_t)r * K + c16;
        #pragma unroll
        for (int i = 0; i < 4; i++) { av[i] = *(const float4*)(ap + i*4);
                                      bv[i] = *(const float4*)(bp + i*4); }
        uint4 h0, l0, h1, l1;
        cvt8(av[0], av[1], h0, l0); cvt8(av[2], av[3], h1, l1);
        STS128A(sb + 0*GM_TILE + sts_off,      h0);
        STS128A(sb + 0*GM_TILE + sts_off + 16, h1);
        STS128A(sb + 1*GM_TILE + sts_off,      l0);
        STS128A(sb + 1*GM_TILE + sts_off + 16, l1);
        cvt8(bv[0], bv[1], h0, l0); cvt8(bv[2], bv[3], h1, l1);
        STS128A(sb + 2*GM_TILE + sts_off,      h0);
        STS128A(sb + 2*GM_TILE + sts_off + 16, h1);
        STS128A(sb + 3*GM_TILE + sts_off,      l0);
        STS128A(sb + 3*GM_TILE + sts_off + 16, l1);
    }
    __syncthreads();

    for (int kc = 0; kc < nch; kc++) {
        int s = kc & 1;
        if (kc + 1 < nch) {
            int k0 = (kc + 1) << 5;
            const float* ap = Ab + (size_t)r * K + k0 + c16;
            const float* bp = Bb + (size_t)r * K + k0 + c16;
            #pragma unroll
            for (int i = 0; i < 4; i++) { av[i] = *(const float4*)(ap + i*4);
                                          bv[i] = *(const float4*)(bp + i*4); }
        }

        uint32_t base = sb + (uint32_t)s * GM_STAGE;
        uint32_t aHi = base, aLo = base + GM_TILE;
        uint32_t bHi = base + 2*GM_TILE, bLo = base + 3*GM_TILE;

        #pragma unroll
        for (int k16 = 0; k16 < 2; k16++) {
            uint32_t ko = (uint32_t)k16 * 32;
            uint32_t ah[8], ax[8], bh[16], bx[16];

            ldsm4(ah + 0, aHi + rpA + ko);
            ldsm4(ah + 4, aHi + rpA + 1280 + ko);
            #pragma unroll
            for (int i = 0; i < 4; i++)
                ldsm4(bh + i*4, bHi + rpB + (uint32_t)i*1280 + ko);
            #pragma unroll
            for (int mt = 0; mt < 2; mt++)
                #pragma unroll
                for (int nt = 0; nt < 8; nt++)
                    mma16816(acc[mt][nt], ah + mt*4, bh + nt*2);

            ldsm4(ax + 0, aLo + rpA + ko);
            ldsm4(ax + 4, aLo + rpA + 1280 + ko);
            #pragma unroll
            for (int mt = 0; mt < 2; mt++)
                #pragma unroll
                for (int nt = 0; nt < 8; nt++)
                    mma16816(acc[mt][nt], ax + mt*4, bh + nt*2);

            #pragma unroll
            for (int i = 0; i < 4; i++)
                ldsm4(bx + i*4, bLo + rpB + (uint32_t)i*1280 + ko);
            #pragma unroll
            for (int mt = 0; mt < 2; mt++)
                #pragma unroll
                for (int nt = 0; nt < 8; nt++)
                    mma16816(acc[mt][nt], ah + mt*4, bx + nt*2);
        }

        if (kc + 1 < nch) {
            uint32_t nbase = sb + (uint32_t)(s ^ 1) * GM_STAGE;
            uint4 h0, l0, h1, l1;
            cvt8(av[0], av[1], h0, l0); cvt8(av[2], av[3], h1, l1);
            STS128A(nbase + 0*GM_TILE + sts_off,      h0);
            STS128A(nbase + 0*GM_TILE + sts_off + 16, h1);
            STS128A(nbase + 1*GM_TILE + sts_off,      l0);
            STS128A(nbase + 1*GM_TILE + sts_off + 16, l1);
            cvt8(bv[0], bv[1], h0, l0); cvt8(bv[2], bv[3], h1, l1);
            STS128A(nbase + 2*GM_TILE + sts_off,      h0);
            STS128A(nbase + 2*GM_TILE + sts_off + 16, h1);
            STS128A(nbase + 3*GM_TILE + sts_off,      l0);
            STS128A(nbase + 3*GM_TILE + sts_off + 16, l1);
        }
        __syncthreads();
    }

    #pragma unroll
    for (int mt = 0; mt < 2; mt++) {
        int gr0 = bm*128 + wm*32 + mt*16 + (lane >> 2);
        #pragma unroll
        for (int nt = 0; nt < 8; nt++) {
            int gc = bn*128 + wn*64 + nt*8 + (lane & 3)*2;
            #pragma unroll
            for (int hfl = 0; hfl < 2; hfl++) {
                int row = gr0 + hfl*8;
                float v0 = acc[mt][nt][hfl*2+0];
                float v1 = acc[mt][nt][hfl*2+1];
                if (FLAGS & F_BIAS) {
                    v0 += __ldg(bias + gc);
                    v1 += __ldg(bias + gc + 1);
                }
                if (FLAGS & F_RES) {
                    float2 rr = *(const float2*)(res + (size_t)row * N + gc);
                    v0 += rr.x; v1 += rr.y;
                }
                if (FLAGS & F_RELU) { v0 = fmaxf(v0, 0.f); v1 = fmaxf(v1, 0.f); }
                float2 o = make_float2(v0, v1);
                *(float2*)(C + (size_t)row * N + gc) = o;
            }
        }
    }
}

// ================= Tensor-core flash attention (bf16x3, causal) =================
// Q tile 128 rows, K/V tiles 64. 256 threads = 8 warps, each warp: 16 q-rows x 64.
// smem rows stride 144 B (72 bf16). Layout:
//   Qhi[128x72] Qlo[128x72] Khi[64x72] Klo[64x72] Vhi[64x72] Vlo[64x72]
#define FAT_QSZ  18432          // 128*144
#define FAT_KSZ  9216           // 64*144
#define FAT_SMEM (2*FAT_QSZ + 4*FAT_KSZ)   // 73728

__global__ __launch_bounds__(256, 1)
void flash_mma_kernel(const float* __restrict__ qkv, float* __restrict__ o)
{
    extern __shared__ __align__(16) char smf[];
    uint32_t sb  = smem_u32(smf);
    uint32_t Qhi = sb,              Qlo = sb + FAT_QSZ;
    uint32_t Khi = sb + 2*FAT_QSZ,  Klo = Khi + FAT_KSZ;
    uint32_t Vhi = Klo + FAT_KSZ,   Vlo = Vhi + FAT_KSZ;

    int tid = threadIdx.x, lane = tid & 31, wid = tid >> 5;
    int qi = blockIdx.x, bh = blockIdx.y;
    int b = bh >> 4, h = bh & 15;

    const float* qbase = qkv + (size_t)b * S_DIM * (3*E_DIM) + h * 64;
    const float* kbase = qbase + E_DIM;
    const float* vbase = qbase + 2*E_DIM;

    // ---- load Q tile (128x64), prescaled by 1/8, hi/lo split ----
    {
        int r = tid >> 1, ch = (tid & 1) * 32;
        const float* qp = qbase + (size_t)(qi*128 + r) * (3*E_DIM) + ch;
        uint32_t base = (uint32_t)(r*144 + ch*2);
        #pragma unroll
        for (int g2 = 0; g2 < 4; g2++) {
            float4 v0 = *(const float4*)(qp + g2*8);
            float4 v1 = *(const float4*)(qp + g2*8 + 4);
            v0.x *= 0.125f; v0.y *= 0.125f; v0.z *= 0.125f; v0.w *= 0.125f;
            v1.x *= 0.125f; v1.y *= 0.125f; v1.z *= 0.125f; v1.w *= 0.125f;
            uint4 hh, ll;
            cvt8(v0, v1, hh, ll);
            STS128A(Qhi + base + g2*16, hh);
            STS128A(Qlo + base + g2*16, ll);
        }
    }
    __syncthreads();

    // ---- Q A-fragments resident in registers (4 k-steps, hi+lo) ----
    uint32_t qh[4][4], ql[4][4];
    {
        uint32_t ra = (uint32_t)((wid*16 + (lane & 15))*144 + (lane >> 4)*16);
        #pragma unroll
        for (int ks = 0; ks < 4; ks++) {
            ldsm4(qh[ks], Qhi + ra + ks*32);
            ldsm4(ql[ks], Qlo + ra + ks*32);
        }
    }

    float oacc[8][4];
    #pragma unroll
    for (int nt = 0; nt < 8; nt++)
        #pragma unroll
        for (int i = 0; i < 4; i++) oacc[nt][i] = 0.f;
    float rm0 = -1e30f, rm1 = -1e30f, rl0 = 0.f, rl1 = 0.f;

    int g = lane >> 3, l8 = lane & 7;
    uint32_t rpB = (uint32_t)((l8 + (g >> 1)*8)*144 + (g & 1)*16);          // K frags
    uint32_t rpV = (uint32_t)((lane & 15)*144 + (lane >> 4)*16);            // V trans frags

    int rowlim = qi*128 + wid*16 + 15;   // max q-row this warp owns
    int nj = 2*qi + 2;

    for (int jt = 0; jt < nj; jt++) {
        __syncthreads();   // previous iteration's readers done with K/V smem

        // ---- load K/V tile jt (64x64 each), hi/lo split ----
        {
            int r = tid >> 2, cg = (tid & 3) * 16;
            const float* kp = kbase + (size_t)(jt*64 + r)*(3*E_DIM) + cg;
            const float* vp = vbase + (size_t)(jt*64 + r)*(3*E_DIM) + cg;
            uint32_t basek = (uint32_t)(r*144 + cg*2);
            #pragma unroll
            for (int g2 = 0; g2 < 2; g2++) {
                float4 a0 = *(const float4*)(kp + g2*8);
                float4 a1 = *(const float4*)(kp + g2*8 + 4);
                uint4 hh, ll;
                cvt8(a0, a1, hh, ll);
                STS128A(Khi + basek + g2*16, hh);
                STS128A(Klo + basek + g2*16, ll);
                a0 = *(const float4*)(vp + g2*8);
                a1 = *(const float4*)(vp + g2*8 + 4);
                cvt8(a0, a1, hh, ll);
                STS128A(Vhi + basek + g2*16, hh);
                STS128A(Vlo + basek + g2*16, ll);
            }
        }
        __syncthreads();

        if (jt*64 > rowlim) continue;   // warp tile fully above diagonal

        // ---- S = Q K^T (3 bf16 products) ----
        float s[8][4];
        #pragma unroll
        for (int nt = 0; nt < 8; nt++)
            #pragma unroll
            for (int i = 0; i < 4; i++) s[nt][i] = 0.f;
        {
            uint32_t kb[16];
            #pragma unroll
            for (int ks = 0; ks < 4; ks++) {
                #pragma unroll
                for (int i = 0; i < 4; i++)
                    ldsm4(kb + 4*i, Khi + rpB + (uint32_t)i*2304 + ks*32);
                #pragma unroll
                for (int nt = 0; nt < 8; nt++)
                    mma16816(s[nt], qh[ks], kb + 2*nt);
                #pragma unroll
                for (int nt = 0; nt < 8; nt++)
                    mma16816(s[nt], ql[ks], kb + 2*nt);
                #pragma unroll
                for (int i = 0; i < 4; i++)
                    ldsm4(kb + 4*i, Klo + rpB + (uint32_t)i*2304 + ks*32);
                #pragma unroll
                for (int nt = 0; nt < 8; nt++)
                    mma16816(s[nt], qh[ks], kb + 2*nt);
            }
        }

        // ---- causal mask (only needed on diagonal tiles) ----
        int row0 = qi*128 + wid*16 + (lane >> 2);
        if (jt >= 2*qi) {
            #pragma unroll
            for (int nt = 0; nt < 8; nt++) {
                int col = jt*64 + nt*8 + (lane & 3)*2;
                if (col     > row0)     s[nt][0] = -1e30f;
                if (col + 1 > row0)     s[nt][1] = -1e30f;
                if (col     > row0 + 8) s[nt][2] = -1e30f;
                if (col + 1 > row0 + 8) s[nt][3] = -1e30f;
            }
        }

        // ---- online softmax (register-resident; rows lane>>2 and +8) ----
        float m0 = -1e30f, m1 = -1e30f;
        #pragma unroll
        for (int nt = 0; nt < 8; nt++) {
            m0 = fmaxf(m0, fmaxf(s[nt][0], s[nt][1]));
            m1 = fmaxf(m1, fmaxf(s[nt][2], s[nt][3]));
        }
        m0 = fmaxf(m0, __shfl_xor_sync(0xffffffffu, m0, 1));
        m0 = fmaxf(m0, __shfl_xor_sync(0xffffffffu, m0, 2));
        m1 = fmaxf(m1, __shfl_xor_sync(0xffffffffu, m1, 1));
        m1 = fmaxf(m1, __shfl_xor_sync(0xffffffffu, m1, 2));

        float mn0 = fmaxf(rm0, m0), mn1 = fmaxf(rm1, m1);
        float al0 = __expf(rm0 - mn0), al1 = __expf(rm1 - mn1);
        rm0 = mn0; rm1 = mn1;

        float sum0 = 0.f, sum1 = 0.f;
        #pragma unroll
        for (int nt = 0; nt < 8; nt++) {
            s[nt][0] = __expf(s[nt][0] - mn0);
            s[nt][1] = __expf(s[nt][1] - mn0);
            s[nt][2] = __expf(s[nt][2] - mn1);
            s[nt][3] = __expf(s[nt][3] - mn1);
            sum0 += s[nt][0] + s[nt][1];
            sum1 += s[nt][2] + s[nt][3];
        }
        sum0 += __shfl_xor_sync(0xffffffffu, sum0, 1);
        sum0 += __shfl_xor_sync(0xffffffffu, sum0, 2);
        sum1 += __shfl_xor_sync(0xffffffffu, sum1, 1);
        sum1 += __shfl_xor_sync(0xffffffffu, sum1, 2);
        rl0 = rl0 * al0 + sum0;
        rl1 = rl1 * al1 + sum1;

        #pragma unroll
        for (int nt = 0; nt < 8; nt++) {
            oacc[nt][0] *= al0; oacc[nt][1] *= al0;
            oacc[nt][2] *= al1; oacc[nt][3] *= al1;
        }

        // ---- P fragments from S accumulators (register-only, hi/lo) ----
        uint32_t ph[4][4], pl[4][4];
        #pragma unroll
        for (int ks = 0; ks < 4; ks++) {
            int j0 = 2*ks, j1 = 2*ks + 1;
            packhl(s[j0][0], s[j0][1], ph[ks][0], pl[ks][0]);
            packhl(s[j0][2], s[j0][3], ph[ks][1], pl[ks][1]);
            packhl(s[j1][0], s[j1][1], ph[ks][2], pl[ks][2]);
            packhl(s[j1][2], s[j1][3], ph[ks][3], pl[ks][3]);
        }

        // ---- O += P V (3 bf16 products, V via trans ldmatrix) ----
        {
            uint32_t vb[16];
            #pragma unroll
            for (int ks = 0; ks < 4; ks++) {
                #pragma unroll
                for (int i = 0; i < 4; i++)
                    ldsm4t(vb + 4*i, Vhi + rpV + (uint32_t)ks*2304 + (uint32_t)i*32);
                #pragma unroll
                for (int nt = 0; nt < 8; nt++)
                    mma16816(oacc[nt], ph[ks], vb + 2*nt);
                #pragma unroll
                for (int nt = 0; nt < 8; nt++)
                    mma16816(oacc[nt], pl[ks], vb + 2*nt);
                #pragma unroll
                for (int i = 0; i < 4; i++)
                    ldsm4t(vb + 4*i, Vlo + rpV + (uint32_t)ks*2304 + (uint32_t)i*32);
                #pragma unroll
                for (int nt = 0; nt < 8; nt++)
                    mma16816(oacc[nt], ph[ks], vb + 2*nt);
            }
        }
    }

    // ---- epilogue: normalize and store ----
    float inv0 = 1.0f / rl0, inv1 = 1.0f / rl1;
    int row0 = qi*128 + wid*16 + (lane >> 2);
    float* ob = o + (size_t)b * S_DIM * E_DIM + h * 64;
    #pragma unroll
    for (int nt = 0; nt < 8; nt++) {
        int col = nt*8 + (lane & 3)*2;
        float2 v0 = make_float2(oacc[nt][0]*inv0, oacc[nt][1]*inv0);
        float2 v1 = make_float2(oacc[nt][2]*inv1, oacc[nt][3]*inv1);
        *(float2*)(ob + (size_t)row0       * E_DIM + col) = v0;
        *(float2*)(ob + (size_t)(row0 + 8) * E_DIM + col) = v1;
    }
}

// ---------------- launch ----------------
extern "C" void kernel_launch(void* const* d_in, const int* in_sizes, int n_in,
                              void* d_out, int out_size)
{
    const float* x      = (const float*)d_in[0];
    const float* w_in   = (const float*)d_in[1];
    const float* w_out  = (const float*)d_in[2];
    const float* w_fc   = (const float*)d_in[3];
    const float* b_fc   = (const float*)d_in[4];
    const float* w_proj = (const float*)d_in[5];
    const float* b_proj = (const float*)d_in[6];
    float* out = (float*)d_out;

    void *ph, *pqkv, *po, *px2, *pm;
    cudaGetSymbolAddress(&ph,   g_h);
    cudaGetSymbolAddress(&pqkv, g_qkv);
    cudaGetSymbolAddress(&po,   g_o);
    cudaGetSymbolAddress(&px2,  g_x2);
    cudaGetSymbolAddress(&pm,   g_m);
    float* bh   = (float*)ph;
    float* bqkv = (float*)pqkv;
    float* bo   = (float*)po;
    float* bx2  = (float*)px2;
    float* bm   = (float*)pm;

    cudaFuncSetAttribute(flash_mma_kernel,
                         cudaFuncAttributeMaxDynamicSharedMemorySize, FAT_SMEM);
    cudaFuncSetAttribute(gemm_mma_kernel<0>,
                         cudaFuncAttributeMaxDynamicSharedMemorySize, GM_SMEM);
    cudaFuncSetAttribute(gemm_mma_kernel<F_RES>,
                         cudaFuncAttributeMaxDynamicSharedMemorySize, GM_SMEM);
    cudaFuncSetAttribute(gemm_mma_kernel<F_BIAS|F_RELU>,
                         cudaFuncAttributeMaxDynamicSharedMemorySize, GM_SMEM);
    cudaFuncSetAttribute(gemm_mma_kernel<F_BIAS|F_RES>,
                         cudaFuncAttributeMaxDynamicSharedMemorySize, GM_SMEM);

    // 1) h = LN(x)
    ln_kernel<<<NROWS, 256>>>(x, bh);
    // 2) qkv = h @ w_in^T         [4096, 3072]
    gemm_mma_kernel<0><<<dim3(3072/128, NROWS/128), 256, GM_SMEM>>>(
        bh, w_in, nullptr, nullptr, bqkv, NROWS, 3072, 1024);
    // 3) o = causal attention(qkv)  — tensor-core flash
    flash_mma_kernel<<<dim3(S_DIM/128, B_DIM*H_DIM), 256, FAT_SMEM>>>(bqkv, bo);
    // 4) x2 = o @ w_out^T + x
    gemm_mma_kernel<F_RES><<<dim3(1024/128, NROWS/128), 256, GM_SMEM>>>(
        bo, w_out, nullptr, x, bx2, NROWS, 1024, 1024);
    // 5) h = LN(x2)
    ln_kernel<<<NROWS, 256>>>(bx2, bh);
    // 6) m = relu(h @ w_fc^T + b_fc)   [4096, 4096]
    gemm_mma_kernel<F_BIAS|F_RELU><<<dim3(4096/128, NROWS/128), 256, GM_SMEM>>>(
        bh, w_fc, b_fc, nullptr, bm, NROWS, 4096, 1024);
    // 7) out = m @ w_proj^T + b_proj + x2
    gemm_mma_kernel<F_BIAS|F_RES><<<dim3(1024/128, NROWS/128), 256, GM_SMEM>>>(
        bm, w_proj, b_proj, bx2, out, NROWS, 1024, 4096);
}

// round 11
// speedup vs baseline: 2.7660x; 1.2829x over previous
#include <cuda_runtime.h>
#include <cuda_bf16.h>
#include <math.h>
#include <stdint.h>

#define E_DIM 1024
#define S_DIM 2048
#define B_DIM 2
#define H_DIM 16
#define NROWS (B_DIM * S_DIM)   // 4096

// ---------------- scratch (no allocations allowed) ----------------
__device__ float g_qkv[(size_t)NROWS * 3 * E_DIM];
__device__ float g_x2 [(size_t)NROWS * E_DIM];
// bf16 hi/lo activation buffers
__device__ __align__(16) unsigned short g_hh[(size_t)NROWS * E_DIM];
__device__ __align__(16) unsigned short g_hl[(size_t)NROWS * E_DIM];
__device__ __align__(16) unsigned short g_oh[(size_t)NROWS * E_DIM];
__device__ __align__(16) unsigned short g_ol[(size_t)NROWS * E_DIM];
__device__ __align__(16) unsigned short g_mh[(size_t)NROWS * 4 * E_DIM];
__device__ __align__(16) unsigned short g_ml[(size_t)NROWS * 4 * E_DIM];
// bf16 hi/lo weights
__device__ __align__(16) unsigned short g_winh [(size_t)3*E_DIM*E_DIM];
__device__ __align__(16) unsigned short g_winl [(size_t)3*E_DIM*E_DIM];
__device__ __align__(16) unsigned short g_wouth[(size_t)E_DIM*E_DIM];
__device__ __align__(16) unsigned short g_woutl[(size_t)E_DIM*E_DIM];
__device__ __align__(16) unsigned short g_wfch [(size_t)4*E_DIM*E_DIM];
__device__ __align__(16) unsigned short g_wfcl [(size_t)4*E_DIM*E_DIM];
__device__ __align__(16) unsigned short g_wprh [(size_t)4*E_DIM*E_DIM];
__device__ __align__(16) unsigned short g_wprl [(size_t)4*E_DIM*E_DIM];

// ================= helpers =================
__device__ __forceinline__ uint32_t smem_u32(const void* p) {
    uint32_t a;
    asm("{ .reg .u64 t; cvta.to.shared.u64 t, %1; cvt.u32.u64 %0, t; }"
        : "=r"(a) : "l"(p));
    return a;
}

__device__ __forceinline__ void ldsm4(uint32_t* r, uint32_t addr) {
    asm volatile("ldmatrix.sync.aligned.m8n8.x4.shared.b16 {%0,%1,%2,%3}, [%4];"
        : "=r"(r[0]), "=r"(r[1]), "=r"(r[2]), "=r"(r[3]) : "r"(addr));
}

__device__ __forceinline__ void ldsm4t(uint32_t* r, uint32_t addr) {
    asm volatile("ldmatrix.sync.aligned.m8n8.x4.trans.shared.b16 {%0,%1,%2,%3}, [%4];"
        : "=r"(r[0]), "=r"(r[1]), "=r"(r[2]), "=r"(r[3]) : "r"(addr));
}

__device__ __forceinline__ void mma16816(float* d, const uint32_t* a, const uint32_t* b) {
    asm volatile(
        "mma.sync.aligned.m16n8k16.row.col.f32.bf16.bf16.f32 "
        "{%0,%1,%2,%3}, {%4,%5,%6,%7}, {%8,%9}, {%0,%1,%2,%3};"
        : "+f"(d[0]), "+f"(d[1]), "+f"(d[2]), "+f"(d[3])
        : "r"(a[0]), "r"(a[1]), "r"(a[2]), "r"(a[3]), "r"(b[0]), "r"(b[1]));
}

#define STS128A(addr, v) \
    asm volatile("st.shared.v4.b32 [%0], {%1, %2, %3, %4};" \
        :: "r"(addr), "r"((v).x), "r"((v).y), "r"((v).z), "r"((v).w) : "memory")

#define CPA16(dst, src) \
    asm volatile("cp.async.cg.shared.global [%0], [%1], 16;" \
        :: "r"(dst), "l"(src) : "memory")
#define CPC() asm volatile("cp.async.commit_group;" ::: "memory")
#define CPW(n) asm volatile("cp.async.wait_group %0;" :: "n"(n) : "memory")

__device__ __forceinline__ void cvt8(float4 v0, float4 v1, uint4& hi, uint4& lo) {
    float x[8] = {v0.x, v0.y, v0.z, v0.w, v1.x, v1.y, v1.z, v1.w};
    uint32_t h[4], l[4];
    #pragma unroll
    for (int i = 0; i < 4; i++) {
        __nv_bfloat16 a = __float2bfloat16_rn(x[2*i]);
        __nv_bfloat16 b = __float2bfloat16_rn(x[2*i+1]);
        __nv_bfloat16 c = __float2bfloat16_rn(x[2*i]   - __bfloat162float(a));
        __nv_bfloat16 d = __float2bfloat16_rn(x[2*i+1] - __bfloat162float(b));
        h[i] = (uint32_t)__bfloat16_as_ushort(a) | ((uint32_t)__bfloat16_as_ushort(b) << 16);
        l[i] = (uint32_t)__bfloat16_as_ushort(c) | ((uint32_t)__bfloat16_as_ushort(d) << 16);
    }
    hi = make_uint4(h[0], h[1], h[2], h[3]);
    lo = make_uint4(l[0], l[1], l[2], l[3]);
}

__device__ __forceinline__ void packhl(float a, float b, uint32_t& hi, uint32_t& lo) {
    __nv_bfloat16 ah = __float2bfloat16_rn(a);
    __nv_bfloat16 bh = __float2bfloat16_rn(b);
    __nv_bfloat16 al = __float2bfloat16_rn(a - __bfloat162float(ah));
    __nv_bfloat16 bl = __float2bfloat16_rn(b - __bfloat162float(bh));
    hi = (uint32_t)__bfloat16_as_ushort(ah) | ((uint32_t)__bfloat16_as_ushort(bh) << 16);
    lo = (uint32_t)__bfloat16_as_ushort(al) | ((uint32_t)__bfloat16_as_ushort(bl) << 16);
}

// ---------------- weight fp32 -> bf16 hi/lo ----------------
__global__ __launch_bounds__(256) void cvtw_kernel(const float* __restrict__ src,
                                                   unsigned short* __restrict__ dh,
                                                   unsigned short* __restrict__ dl,
                                                   int n8)
{
    for (int i = blockIdx.x * blockDim.x + threadIdx.x; i < n8;
         i += gridDim.x * blockDim.x) {
        float4 v0 = *(const float4*)(src + (size_t)i * 8);
        float4 v1 = *(const float4*)(src + (size_t)i * 8 + 4);
        uint4 h, l;
        cvt8(v0, v1, h, l);
        ((uint4*)dh)[i] = h;
        ((uint4*)dl)[i] = l;
    }
}

// ---------------- LayerNorm -> bf16 hi/lo ----------------
__global__ __launch_bounds__(256) void ln_kernel(const float* __restrict__ x,
                                                 unsigned short* __restrict__ yh,
                                                 unsigned short* __restrict__ yl)
{
    int row = blockIdx.x;
    int tid = threadIdx.x;
    const float* xr = x + (size_t)row * E_DIM;

    float4 v = *(const float4*)(xr + tid * 4);
    float s  = v.x + v.y + v.z + v.w;
    float ss = v.x*v.x + v.y*v.y + v.z*v.z + v.w*v.w;

    #pragma unroll
    for (int off = 16; off > 0; off >>= 1) {
        s  += __shfl_xor_sync(0xffffffffu, s,  off);
        ss += __shfl_xor_sync(0xffffffffu, ss, off);
    }

    __shared__ float rs[8], rss[8], stat[2];
    int wid = tid >> 5, lane = tid & 31;
    if (lane == 0) { rs[wid] = s; rss[wid] = ss; }
    __syncthreads();
    if (tid == 0) {
        float t = 0.f, tt = 0.f;
        #pragma unroll
        for (int i = 0; i < 8; i++) { t += rs[i]; tt += rss[i]; }
        float mean = t * (1.0f / E_DIM);
        float var  = tt * (1.0f / E_DIM) - mean * mean;
        stat[0] = mean;
        stat[1] = rsqrtf(var + 1e-5f);
    }
    __syncthreads();
    float mean = stat[0], rstd = stat[1];
    float o0 = (v.x - mean) * rstd, o1 = (v.y - mean) * rstd;
    float o2 = (v.z - mean) * rstd, o3 = (v.w - mean) * rstd;
    uint32_t h0, l0, h1, l1;
    packhl(o0, o1, h0, l0);
    packhl(o2, o3, h1, l1);
    uint2 hh = make_uint2(h0, h1), ll = make_uint2(l0, l1);
    *(uint2*)(yh + (size_t)row * E_DIM + tid * 4) = hh;
    *(uint2*)(yl + (size_t)row * E_DIM + tid * 4) = ll;
}

// ================= bf16x3 GEMM, cp.async pipeline =================
// C[M,N] = A[M,K] @ B[N,K]^T; A,B given as bf16 hi/lo pairs.
// Tile 128x128, BK=32, 256 threads (8 warps, 32x64 each), 2-stage cp.async.
#define F_BIAS  1
#define F_RELU  2
#define F_RES   4
#define F_OUTBF 8

#define GB_TILE  10240              // 128 rows x 80 B
#define GB_STAGE (4 * GB_TILE)      // 40960
#define GB_SMEM  (2 * GB_STAGE)     // 81920

template<int FLAGS>
__global__ __launch_bounds__(256, 2)
void gemm_bf16_kernel(const unsigned short* __restrict__ Ah,
                      const unsigned short* __restrict__ Al,
                      const unsigned short* __restrict__ Bh,
                      const unsigned short* __restrict__ Bl,
                      const float* __restrict__ bias, const float* __restrict__ res,
                      float* __restrict__ C,
                      unsigned short* __restrict__ Ch, unsigned short* __restrict__ Cl,
                      int M, int N, int K)
{
    extern __shared__ __align__(16) char smem[];
    uint32_t sb = smem_u32(smem);

    int tid = threadIdx.x;
    int lane = tid & 31, wid = tid >> 5;
    int wm = wid >> 1, wn = wid & 1;
    int bn = blockIdx.x, bm = blockIdx.y;

    // cp.async mapping: thread -> rows r0 (=tid>>2) and r0+64, 16B col chunk c0
    int r0 = tid >> 2, c0 = tid & 3;
    uint32_t so = (uint32_t)(r0 * 80 + c0 * 16);
    size_t goff = (size_t)r0 * K + c0 * 8;
    const unsigned short* pA0 = Ah + (size_t)(bm * 128) * K + goff;
    const unsigned short* pL0 = Al + (size_t)(bm * 128) * K + goff;
    const unsigned short* pB0 = Bh + (size_t)(bn * 128) * K + goff;
    const unsigned short* pX0 = Bl + (size_t)(bn * 128) * K + goff;
    size_t half = (size_t)64 * K;

    uint32_t rpA = (uint32_t)((wm * 32 + (lane & 15)) * 80 + (lane >> 4) * 16);
    int g = lane >> 3, l8 = lane & 7;
    uint32_t rpB = (uint32_t)((wn * 64 + l8 + (g >> 1) * 8) * 80 + (g & 1) * 16);

    float acc[2][8][4];
    #pragma unroll
    for (int mt = 0; mt < 2; mt++)
        #pragma unroll
        for (int nt = 0; nt < 8; nt++)
            #pragma unroll
            for (int i = 0; i < 4; i++) acc[mt][nt][i] = 0.f;

    int nch = K >> 5;

    #define GB_ISSUE(kc) do {                                            \
        if ((kc) < nch) {                                                \
            uint32_t sa = sb + (uint32_t)((kc) & 1) * GB_STAGE;          \
            int off = (kc) * 32;                                         \
            CPA16(sa + so,                        pA0 + off);            \
            CPA16(sa + so + 5120,                 pA0 + half + off);     \
            CPA16(sa + GB_TILE + so,              pL0 + off);            \
            CPA16(sa + GB_TILE + so + 5120,       pL0 + half + off);     \
            CPA16(sa + 2*GB_TILE + so,            pB0 + off);            \
            CPA16(sa + 2*GB_TILE + so + 5120,     pB0 + half + off);     \
            CPA16(sa + 3*GB_TILE + so,            pX0 + off);            \
            CPA16(sa + 3*GB_TILE + so + 5120,     pX0 + half + off);     \
        }                                                                \
        CPC();                                                           \
    } while (0)

    GB_ISSUE(0);
    GB_ISSUE(1);

    for (int kc = 0; kc < nch; kc++) {
        CPW(1);
        __syncthreads();

        uint32_t base = sb + (uint32_t)(kc & 1) * GB_STAGE;
        uint32_t aHi = base, aLo = base + GB_TILE;
        uint32_t bHi = base + 2*GB_TILE, bLo = base + 3*GB_TILE;

        #pragma unroll
        for (int k16 = 0; k16 < 2; k16++) {
            uint32_t ko = (uint32_t)k16 * 32;
            uint32_t ah[8], ax[8], bb[16];

            ldsm4(ah + 0, aHi + rpA + ko);
            ldsm4(ah + 4, aHi + rpA + 1280 + ko);
            ldsm4(ax + 0, aLo + rpA + ko);
            ldsm4(ax + 4, aLo + rpA + 1280 + ko);
            #pragma unroll
            for (int i = 0; i < 4; i++)
                ldsm4(bb + i*4, bHi + rpB + (uint32_t)i*1280 + ko);
            #pragma unroll
            for (int mt = 0; mt < 2; mt++)
                #pragma unroll
                for (int nt = 0; nt < 8; nt++)
                    mma16816(acc[mt][nt], ah + mt*4, bb + nt*2);
            #pragma unroll
            for (int mt = 0; mt < 2; mt++)
                #pragma unroll
                for (int nt = 0; nt < 8; nt++)
                    mma16816(acc[mt][nt], ax + mt*4, bb + nt*2);
            #pragma unroll
            for (int i = 0; i < 4; i++)
                ldsm4(bb + i*4, bLo + rpB + (uint32_t)i*1280 + ko);
            #pragma unroll
            for (int mt = 0; mt < 2; mt++)
                #pragma unroll
                for (int nt = 0; nt < 8; nt++)
                    mma16816(acc[mt][nt], ah + mt*4, bb + nt*2);
        }

        __syncthreads();
        GB_ISSUE(kc + 2);
    }
    #undef GB_ISSUE

    // ---- epilogue ----
    #pragma unroll
    for (int mt = 0; mt < 2; mt++) {
        int gr0 = bm*128 + wm*32 + mt*16 + (lane >> 2);
        #pragma unroll
        for (int nt = 0; nt < 8; nt++) {
            int gc = bn*128 + wn*64 + nt*8 + (lane & 3)*2;
            #pragma unroll
            for (int hfl = 0; hfl < 2; hfl++) {
                int row = gr0 + hfl*8;
                float v0 = acc[mt][nt][hfl*2+0];
                float v1 = acc[mt][nt][hfl*2+1];
                if (FLAGS & F_BIAS) {
                    v0 += __ldg(bias + gc);
                    v1 += __ldg(bias + gc + 1);
                }
                if (FLAGS & F_RES) {
                    float2 rr = *(const float2*)(res + (size_t)row * N + gc);
                    v0 += rr.x; v1 += rr.y;
                }
                if (FLAGS & F_RELU) { v0 = fmaxf(v0, 0.f); v1 = fmaxf(v1, 0.f); }
                if (FLAGS & F_OUTBF) {
                    uint32_t h, l;
                    packhl(v0, v1, h, l);
                    *(uint32_t*)(Ch + (size_t)row * N + gc) = h;
                    *(uint32_t*)(Cl + (size_t)row * N + gc) = l;
                } else {
                    float2 o = make_float2(v0, v1);
                    *(float2*)(C + (size_t)row * N + gc) = o;
                }
            }
        }
    }
}

// ================= Tensor-core flash attention (bf16x3, causal) =================
#define FAT_QSZ  18432          // 128*144
#define FAT_KSZ  9216           // 64*144
#define FAT_SMEM (2*FAT_QSZ + 4*FAT_KSZ)   // 73728

__global__ __launch_bounds__(256, 1)
void flash_mma_kernel(const float* __restrict__ qkv,
                      unsigned short* __restrict__ oh,
                      unsigned short* __restrict__ ol)
{
    extern __shared__ __align__(16) char smf[];
    uint32_t sb  = smem_u32(smf);
    uint32_t Qhi = sb,              Qlo = sb + FAT_QSZ;
    uint32_t Khi = sb + 2*FAT_QSZ,  Klo = Khi + FAT_KSZ;
    uint32_t Vhi = Klo + FAT_KSZ,   Vlo = Vhi + FAT_KSZ;

    int tid = threadIdx.x, lane = tid & 31, wid = tid >> 5;
    int qi = blockIdx.x, bh = blockIdx.y;
    int b = bh >> 4, h = bh & 15;

    const float* qbase = qkv + (size_t)b * S_DIM * (3*E_DIM) + h * 64;
    const float* kbase = qbase + E_DIM;
    const float* vbase = qbase + 2*E_DIM;

    {
        int r = tid >> 1, ch = (tid & 1) * 32;
        const float* qp = qbase + (size_t)(qi*128 + r) * (3*E_DIM) + ch;
        uint32_t base = (uint32_t)(r*144 + ch*2);
        #pragma unroll
        for (int g2 = 0; g2 < 4; g2++) {
            float4 v0 = *(const float4*)(qp + g2*8);
            float4 v1 = *(const float4*)(qp + g2*8 + 4);
            v0.x *= 0.125f; v0.y *= 0.125f; v0.z *= 0.125f; v0.w *= 0.125f;
            v1.x *= 0.125f; v1.y *= 0.125f; v1.z *= 0.125f; v1.w *= 0.125f;
            uint4 hh, ll;
            cvt8(v0, v1, hh, ll);
            STS128A(Qhi + base + g2*16, hh);
            STS128A(Qlo + base + g2*16, ll);
        }
    }
    __syncthreads();

    uint32_t qh[4][4], ql[4][4];
    {
        uint32_t ra = (uint32_t)((wid*16 + (lane & 15))*144 + (lane >> 4)*16);
        #pragma unroll
        for (int ks = 0; ks < 4; ks++) {
            ldsm4(qh[ks], Qhi + ra + ks*32);
            ldsm4(ql[ks], Qlo + ra + ks*32);
        }
    }

    float oacc[8][4];
    #pragma unroll
    for (int nt = 0; nt < 8; nt++)
        #pragma unroll
        for (int i = 0; i < 4; i++) oacc[nt][i] = 0.f;
    float rm0 = -1e30f, rm1 = -1e30f, rl0 = 0.f, rl1 = 0.f;

    int g = lane >> 3, l8 = lane & 7;
    uint32_t rpB = (uint32_t)((l8 + (g >> 1)*8)*144 + (g & 1)*16);
    uint32_t rpV = (uint32_t)((lane & 15)*144 + (lane >> 4)*16);

    int rowlim = qi*128 + wid*16 + 15;
    int nj = 2*qi + 2;

    for (int jt = 0; jt < nj; jt++) {
        __syncthreads();

        {
            int r = tid >> 2, cg = (tid & 3) * 16;
            const float* kp = kbase + (size_t)(jt*64 + r)*(3*E_DIM) + cg;
            const float* vp = vbase + (size_t)(jt*64 + r)*(3*E_DIM) + cg;
            uint32_t basek = (uint32_t)(r*144 + cg*2);
            #pragma unroll
            for (int g2 = 0; g2 < 2; g2++) {
                float4 a0 = *(const float4*)(kp + g2*8);
                float4 a1 = *(const float4*)(kp + g2*8 + 4);
                uint4 hh, ll;
                cvt8(a0, a1, hh, ll);
                STS128A(Khi + basek + g2*16, hh);
                STS128A(Klo + basek + g2*16, ll);
                a0 = *(const float4*)(vp + g2*8);
                a1 = *(const float4*)(vp + g2*8 + 4);
                cvt8(a0, a1, hh, ll);
                STS128A(Vhi + basek + g2*16, hh);
                STS128A(Vlo + basek + g2*16, ll);
            }
        }
        __syncthreads();

        if (jt*64 > rowlim) continue;

        float s[8][4];
        #pragma unroll
        for (int nt = 0; nt < 8; nt++)
            #pragma unroll
            for (int i = 0; i < 4; i++) s[nt][i] = 0.f;
        {
            uint32_t kb[16];
            #pragma unroll
            for (int ks = 0; ks < 4; ks++) {
                #pragma unroll
                for (int i = 0; i < 4; i++)
                    ldsm4(kb + 4*i, Khi + rpB + (uint32_t)i*2304 + ks*32);
                #pragma unroll
                for (int nt = 0; nt < 8; nt++)
                    mma16816(s[nt], qh[ks], kb + 2*nt);
                #pragma unroll
                for (int nt = 0; nt < 8; nt++)
                    mma16816(s[nt], ql[ks], kb + 2*nt);
                #pragma unroll
                for (int i = 0; i < 4; i++)
                    ldsm4(kb + 4*i, Klo + rpB + (uint32_t)i*2304 + ks*32);
                #pragma unroll
                for (int nt = 0; nt < 8; nt++)
                    mma16816(s[nt], qh[ks], kb + 2*nt);
            }
        }

        int row0 = qi*128 + wid*16 + (lane >> 2);
        if (jt >= 2*qi) {
            #pragma unroll
            for (int nt = 0; nt < 8; nt++) {
                int col = jt*64 + nt*8 + (lane & 3)*2;
                if (col     > row0)     s[nt][0] = -1e30f;
                if (col + 1 > row0)     s[nt][1] = -1e30f;
                if (col     > row0 + 8) s[nt][2] = -1e30f;
                if (col + 1 > row0 + 8) s[nt][3] = -1e30f;
            }
        }

        float m0 = -1e30f, m1 = -1e30f;
        #pragma unroll
        for (int nt = 0; nt < 8; nt++) {
            m0 = fmaxf(m0, fmaxf(s[nt][0], s[nt][1]));
            m1 = fmaxf(m1, fmaxf(s[nt][2], s[nt][3]));
        }
        m0 = fmaxf(m0, __shfl_xor_sync(0xffffffffu, m0, 1));
        m0 = fmaxf(m0, __shfl_xor_sync(0xffffffffu, m0, 2));
        m1 = fmaxf(m1, __shfl_xor_sync(0xffffffffu, m1, 1));
        m1 = fmaxf(m1, __shfl_xor_sync(0xffffffffu, m1, 2));

        float mn0 = fmaxf(rm0, m0), mn1 = fmaxf(rm1, m1);
        float al0 = __expf(rm0 - mn0), al1 = __expf(rm1 - mn1);
        rm0 = mn0; rm1 = mn1;

        float sum0 = 0.f, sum1 = 0.f;
        #pragma unroll
        for (int nt = 0; nt < 8; nt++) {
            s[nt][0] = __expf(s[nt][0] - mn0);
            s[nt][1] = __expf(s[nt][1] - mn0);
            s[nt][2] = __expf(s[nt][2] - mn1);
            s[nt][3] = __expf(s[nt][3] - mn1);
            sum0 += s[nt][0] + s[nt][1];
            sum1 += s[nt][2] + s[nt][3];
        }
        sum0 += __shfl_xor_sync(0xffffffffu, sum0, 1);
        sum0 += __shfl_xor_sync(0xffffffffu, sum0, 2);
        sum1 += __shfl_xor_sync(0xffffffffu, sum1, 1);
        sum1 += __shfl_xor_sync(0xffffffffu, sum1, 2);
        rl0 = rl0 * al0 + sum0;
        rl1 = rl1 * al1 + sum1;

        #pragma unroll
        for (int nt = 0; nt < 8; nt++) {
            oacc[nt][0] *= al0; oacc[nt][1] *= al0;
            oacc[nt][2] *= al1; oacc[nt][3] *= al1;
        }

        uint32_t ph[4][4], pl[4][4];
        #pragma unroll
        for (int ks = 0; ks < 4; ks++) {
            int j0 = 2*ks, j1 = 2*ks + 1;
            packhl(s[j0][0], s[j0][1], ph[ks][0], pl[ks][0]);
            packhl(s[j0][2], s[j0][3], ph[ks][1], pl[ks][1]);
            packhl(s[j1][0], s[j1][1], ph[ks][2], pl[ks][2]);
            packhl(s[j1][2], s[j1][3], ph[ks][3], pl[ks][3]);
        }

        {
            uint32_t vb[16];
            #pragma unroll
            for (int ks = 0; ks < 4; ks++) {
                #pragma unroll
                for (int i = 0; i < 4; i++)
                    ldsm4t(vb + 4*i, Vhi + rpV + (uint32_t)ks*2304 + (uint32_t)i*32);
                #pragma unroll
                for (int nt = 0; nt < 8; nt++)
                    mma16816(oacc[nt], ph[ks], vb + 2*nt);
                #pragma unroll
                for (int nt = 0; nt < 8; nt++)
                    mma16816(oacc[nt], pl[ks], vb + 2*nt);
                #pragma unroll
                for (int i = 0; i < 4; i++)
                    ldsm4t(vb + 4*i, Vlo + rpV + (uint32_t)ks*2304 + (uint32_t)i*32);
                #pragma unroll
                for (int nt = 0; nt < 8; nt++)
                    mma16816(oacc[nt], ph[ks], vb + 2*nt);
            }
        }
    }

    // ---- epilogue: normalize, write bf16 hi/lo directly ----
    float inv0 = 1.0f / rl0, inv1 = 1.0f / rl1;
    int row0 = qi*128 + wid*16 + (lane >> 2);
    size_t obase = (size_t)b * S_DIM * E_DIM + h * 64;
    #pragma unroll
    for (int nt = 0; nt < 8; nt++) {
        int col = nt*8 + (lane & 3)*2;
        uint32_t h0, l0, h1, l1;
        packhl(oacc[nt][0]*inv0, oacc[nt][1]*inv0, h0, l0);
        packhl(oacc[nt][2]*inv1, oacc[nt][3]*inv1, h1, l1);
        *(uint32_t*)(oh + obase + (size_t)row0       * E_DIM + col) = h0;
        *(uint32_t*)(ol + obase + (size_t)row0       * E_DIM + col) = l0;
        *(uint32_t*)(oh + obase + (size_t)(row0 + 8) * E_DIM + col) = h1;
        *(uint32_t*)(ol + obase + (size_t)(row0 + 8) * E_DIM + col) = l1;
    }
}

// ---------------- launch ----------------
extern "C" void kernel_launch(void* const* d_in, const int* in_sizes, int n_in,
                              void* d_out, int out_size)
{
    const float* x      = (const float*)d_in[0];
    const float* w_in   = (const float*)d_in[1];
    const float* w_out  = (const float*)d_in[2];
    const float* w_fc   = (const float*)d_in[3];
    const float* b_fc   = (const float*)d_in[4];
    const float* w_proj = (const float*)d_in[5];
    const float* b_proj = (const float*)d_in[6];
    float* out = (float*)d_out;

    void *pqkv, *px2, *phh, *phl, *poh, *pol, *pmh, *pml;
    void *pwinh, *pwinl, *pwouth, *pwoutl, *pwfch, *pwfcl, *pwprh, *pwprl;
    cudaGetSymbolAddress(&pqkv, g_qkv);
    cudaGetSymbolAddress(&px2,  g_x2);
    cudaGetSymbolAddress(&phh,  g_hh);   cudaGetSymbolAddress(&phl,  g_hl);
    cudaGetSymbolAddress(&poh,  g_oh);   cudaGetSymbolAddress(&pol,  g_ol);
    cudaGetSymbolAddress(&pmh,  g_mh);   cudaGetSymbolAddress(&pml,  g_ml);
    cudaGetSymbolAddress(&pwinh,  g_winh);  cudaGetSymbolAddress(&pwinl,  g_winl);
    cudaGetSymbolAddress(&pwouth, g_wouth); cudaGetSymbolAddress(&pwoutl, g_woutl);
    cudaGetSymbolAddress(&pwfch,  g_wfch);  cudaGetSymbolAddress(&pwfcl,  g_wfcl);
    cudaGetSymbolAddress(&pwprh,  g_wprh);  cudaGetSymbolAddress(&pwprl,  g_wprl);

    float* bqkv = (float*)pqkv;
    float* bx2  = (float*)px2;
    unsigned short *bhh = (unsigned short*)phh, *bhl = (unsigned short*)phl;
    unsigned short *boh = (unsigned short*)poh, *bol = (unsigned short*)pol;
    unsigned short *bmh = (unsigned short*)pmh, *bml = (unsigned short*)pml;
    unsigned short *winh = (unsigned short*)pwinh, *winl = (unsigned short*)pwinl;
    unsigned short *wouth = (unsigned short*)pwouth, *woutl = (unsigned short*)pwoutl;
    unsigned short *wfch = (unsigned short*)pwfch, *wfcl = (unsigned short*)pwfcl;
    unsigned short *wprh = (unsigned short*)pwprh, *wprl = (unsigned short*)pwprl;

    cudaFuncSetAttribute(flash_mma_kernel,
                         cudaFuncAttributeMaxDynamicSharedMemorySize, FAT_SMEM);
    cudaFuncSetAttribute(gemm_bf16_kernel<0>,
                         cudaFuncAttributeMaxDynamicSharedMemorySize, GB_SMEM);
    cudaFuncSetAttribute(gemm_bf16_kernel<F_RES>,
                         cudaFuncAttributeMaxDynamicSharedMemorySize, GB_SMEM);
    cudaFuncSetAttribute(gemm_bf16_kernel<F_BIAS|F_RELU|F_OUTBF>,
                         cudaFuncAttributeMaxDynamicSharedMemorySize, GB_SMEM);
    cudaFuncSetAttribute(gemm_bf16_kernel<F_BIAS|F_RES>,
                         cudaFuncAttributeMaxDynamicSharedMemorySize, GB_SMEM);

    // 0) weight conversions (cheap, bandwidth-bound)
    cvtw_kernel<<<1024, 256>>>(w_in,   winh,  winl,  3*E_DIM*E_DIM/8);
    cvtw_kernel<<<1024, 256>>>(w_out,  wouth, woutl, E_DIM*E_DIM/8);
    cvtw_kernel<<<1024, 256>>>(w_fc,   wfch,  wfcl,  4*E_DIM*E_DIM/8);
    cvtw_kernel<<<1024, 256>>>(w_proj, wprh,  wprl,  4*E_DIM*E_DIM/8);

    // 1) h = LN(x) -> bf16 hi/lo
    ln_kernel<<<NROWS, 256>>>(x, bhh, bhl);
    // 2) qkv = h @ w_in^T   (fp32 out for flash)
    gemm_bf16_kernel<0><<<dim3(3072/128, NROWS/128), 256, GB_SMEM>>>(
        bhh, bhl, winh, winl, nullptr, nullptr, bqkv, nullptr, nullptr,
        NROWS, 3072, 1024);
    // 3) o = causal attention(qkv) -> bf16 hi/lo
    flash_mma_kernel<<<dim3(S_DIM/128, B_DIM*H_DIM), 256, FAT_SMEM>>>(bqkv, boh, bol);
    // 4) x2 = o @ w_out^T + x   (fp32)
    gemm_bf16_kernel<F_RES><<<dim3(1024/128, NROWS/128), 256, GB_SMEM>>>(
        boh, bol, wouth, woutl, nullptr, x, bx2, nullptr, nullptr,
        NROWS, 1024, 1024);
    // 5) h2 = LN(x2) -> bf16 hi/lo (reuse h buffers)
    ln_kernel<<<NROWS, 256>>>(bx2, bhh, bhl);
    // 6) m = relu(h2 @ w_fc^T + b_fc) -> bf16 hi/lo only
    gemm_bf16_kernel<F_BIAS|F_RELU|F_OUTBF><<<dim3(4096/128, NROWS/128), 256, GB_SMEM>>>(
        bhh, bhl, wfch, wfcl, b_fc, nullptr, nullptr, bmh, bml,
        NROWS, 4096, 1024);
    // 7) out = m @ w_proj^T + b_proj + x2   (fp32)
    gemm_bf16_kernel<F_BIAS|F_RES><<<dim3(1024/128, NROWS/128), 256, GB_SMEM>>>(
        bmh, bml, wprh, wprl, b_proj, bx2, out, nullptr, nullptr,
        NROWS, 1024, 4096);
}

// round 12
// speedup vs baseline: 2.8839x; 1.0426x over previous
#include <cuda_runtime.h>
#include <cuda_bf16.h>
#include <math.h>
#include <stdint.h>

#define E_DIM 1024
#define S_DIM 2048
#define B_DIM 2
#define H_DIM 16
#define NROWS (B_DIM * S_DIM)   // 4096

// ---------------- scratch (no allocations allowed) ----------------
__device__ float g_x2 [(size_t)NROWS * E_DIM];
// bf16 hi/lo activation buffers
__device__ __align__(16) unsigned short g_hh[(size_t)NROWS * E_DIM];
__device__ __align__(16) unsigned short g_hl[(size_t)NROWS * E_DIM];
__device__ __align__(16) unsigned short g_qkvh[(size_t)NROWS * 3 * E_DIM];
__device__ __align__(16) unsigned short g_qkvl[(size_t)NROWS * 3 * E_DIM];
__device__ __align__(16) unsigned short g_oh[(size_t)NROWS * E_DIM];
__device__ __align__(16) unsigned short g_ol[(size_t)NROWS * E_DIM];
__device__ __align__(16) unsigned short g_mh[(size_t)NROWS * 4 * E_DIM];
__device__ __align__(16) unsigned short g_ml[(size_t)NROWS * 4 * E_DIM];
// bf16 hi/lo weights
__device__ __align__(16) unsigned short g_winh [(size_t)3*E_DIM*E_DIM];
__device__ __align__(16) unsigned short g_winl [(size_t)3*E_DIM*E_DIM];
__device__ __align__(16) unsigned short g_wouth[(size_t)E_DIM*E_DIM];
__device__ __align__(16) unsigned short g_woutl[(size_t)E_DIM*E_DIM];
__device__ __align__(16) unsigned short g_wfch [(size_t)4*E_DIM*E_DIM];
__device__ __align__(16) unsigned short g_wfcl [(size_t)4*E_DIM*E_DIM];
__device__ __align__(16) unsigned short g_wprh [(size_t)4*E_DIM*E_DIM];
__device__ __align__(16) unsigned short g_wprl [(size_t)4*E_DIM*E_DIM];

// ================= helpers =================
__device__ __forceinline__ uint32_t smem_u32(const void* p) {
    uint32_t a;
    asm("{ .reg .u64 t; cvta.to.shared.u64 t, %1; cvt.u32.u64 %0, t; }"
        : "=r"(a) : "l"(p));
    return a;
}

__device__ __forceinline__ void ldsm4(uint32_t* r, uint32_t addr) {
    asm volatile("ldmatrix.sync.aligned.m8n8.x4.shared.b16 {%0,%1,%2,%3}, [%4];"
        : "=r"(r[0]), "=r"(r[1]), "=r"(r[2]), "=r"(r[3]) : "r"(addr));
}

__device__ __forceinline__ void ldsm4t(uint32_t* r, uint32_t addr) {
    asm volatile("ldmatrix.sync.aligned.m8n8.x4.trans.shared.b16 {%0,%1,%2,%3}, [%4];"
        : "=r"(r[0]), "=r"(r[1]), "=r"(r[2]), "=r"(r[3]) : "r"(addr));
}

__device__ __forceinline__ void mma16816(float* d, const uint32_t* a, const uint32_t* b) {
    asm volatile(
        "mma.sync.aligned.m16n8k16.row.col.f32.bf16.bf16.f32 "
        "{%0,%1,%2,%3}, {%4,%5,%6,%7}, {%8,%9}, {%0,%1,%2,%3};"
        : "+f"(d[0]), "+f"(d[1]), "+f"(d[2]), "+f"(d[3])
        : "r"(a[0]), "r"(a[1]), "r"(a[2]), "r"(a[3]), "r"(b[0]), "r"(b[1]));
}

#define CPA16(dst, src) \
    asm volatile("cp.async.cg.shared.global [%0], [%1], 16;" \
        :: "r"(dst), "l"(src) : "memory")
#define CPC() asm volatile("cp.async.commit_group;" ::: "memory")
#define CPW(n) asm volatile("cp.async.wait_group %0;" :: "n"(n) : "memory")

__device__ __forceinline__ void cvt8(float4 v0, float4 v1, uint4& hi, uint4& lo) {
    float x[8] = {v0.x, v0.y, v0.z, v0.w, v1.x, v1.y, v1.z, v1.w};
    uint32_t h[4], l[4];
    #pragma unroll
    for (int i = 0; i < 4; i++) {
        __nv_bfloat16 a = __float2bfloat16_rn(x[2*i]);
        __nv_bfloat16 b = __float2bfloat16_rn(x[2*i+1]);
        __nv_bfloat16 c = __float2bfloat16_rn(x[2*i]   - __bfloat162float(a));
        __nv_bfloat16 d = __float2bfloat16_rn(x[2*i+1] - __bfloat162float(b));
        h[i] = (uint32_t)__bfloat16_as_ushort(a) | ((uint32_t)__bfloat16_as_ushort(b) << 16);
        l[i] = (uint32_t)__bfloat16_as_ushort(c) | ((uint32_t)__bfloat16_as_ushort(d) << 16);
    }
    hi = make_uint4(h[0], h[1], h[2], h[3]);
    lo = make_uint4(l[0], l[1], l[2], l[3]);
}

__device__ __forceinline__ void packhl(float a, float b, uint32_t& hi, uint32_t& lo) {
    __nv_bfloat16 ah = __float2bfloat16_rn(a);
    __nv_bfloat16 bh = __float2bfloat16_rn(b);
    __nv_bfloat16 al = __float2bfloat16_rn(a - __bfloat162float(ah));
    __nv_bfloat16 bl = __float2bfloat16_rn(b - __bfloat162float(bh));
    hi = (uint32_t)__bfloat16_as_ushort(ah) | ((uint32_t)__bfloat16_as_ushort(bh) << 16);
    lo = (uint32_t)__bfloat16_as_ushort(al) | ((uint32_t)__bfloat16_as_ushort(bl) << 16);
}

// ---------------- weight fp32 -> bf16 hi/lo ----------------
__global__ __launch_bounds__(256) void cvtw_kernel(const float* __restrict__ src,
                                                   unsigned short* __restrict__ dh,
                                                   unsigned short* __restrict__ dl,
                                                   int n8)
{
    for (int i = blockIdx.x * blockDim.x + threadIdx.x; i < n8;
         i += gridDim.x * blockDim.x) {
        float4 v0 = *(const float4*)(src + (size_t)i * 8);
        float4 v1 = *(const float4*)(src + (size_t)i * 8 + 4);
        uint4 h, l;
        cvt8(v0, v1, h, l);
        ((uint4*)dh)[i] = h;
        ((uint4*)dl)[i] = l;
    }
}

// ---------------- LayerNorm -> bf16 hi/lo ----------------
__global__ __launch_bounds__(256) void ln_kernel(const float* __restrict__ x,
                                                 unsigned short* __restrict__ yh,
                                                 unsigned short* __restrict__ yl)
{
    int row = blockIdx.x;
    int tid = threadIdx.x;
    const float* xr = x + (size_t)row * E_DIM;

    float4 v = *(const float4*)(xr + tid * 4);
    float s  = v.x + v.y + v.z + v.w;
    float ss = v.x*v.x + v.y*v.y + v.z*v.z + v.w*v.w;

    #pragma unroll
    for (int off = 16; off > 0; off >>= 1) {
        s  += __shfl_xor_sync(0xffffffffu, s,  off);
        ss += __shfl_xor_sync(0xffffffffu, ss, off);
    }

    __shared__ float rs[8], rss[8], stat[2];
    int wid = tid >> 5, lane = tid & 31;
    if (lane == 0) { rs[wid] = s; rss[wid] = ss; }
    __syncthreads();
    if (tid == 0) {
        float t = 0.f, tt = 0.f;
        #pragma unroll
        for (int i = 0; i < 8; i++) { t += rs[i]; tt += rss[i]; }
        float mean = t * (1.0f / E_DIM);
        float var  = tt * (1.0f / E_DIM) - mean * mean;
        stat[0] = mean;
        stat[1] = rsqrtf(var + 1e-5f);
    }
    __syncthreads();
    float mean = stat[0], rstd = stat[1];
    float o0 = (v.x - mean) * rstd, o1 = (v.y - mean) * rstd;
    float o2 = (v.z - mean) * rstd, o3 = (v.w - mean) * rstd;
    uint32_t h0, l0, h1, l1;
    packhl(o0, o1, h0, l0);
    packhl(o2, o3, h1, l1);
    uint2 hh = make_uint2(h0, h1), ll = make_uint2(l0, l1);
    *(uint2*)(yh + (size_t)row * E_DIM + tid * 4) = hh;
    *(uint2*)(yl + (size_t)row * E_DIM + tid * 4) = ll;
}

// ================= bf16x3 GEMM, cp.async pipeline (R11, proven) =================
#define F_BIAS  1
#define F_RELU  2
#define F_RES   4
#define F_OUTBF 8

#define GB_TILE  10240
#define GB_STAGE (4 * GB_TILE)
#define GB_SMEM  (2 * GB_STAGE)

template<int FLAGS>
__global__ __launch_bounds__(256, 2)
void gemm_bf16_kernel(const unsigned short* __restrict__ Ah,
                      const unsigned short* __restrict__ Al,
                      const unsigned short* __restrict__ Bh,
                      const unsigned short* __restrict__ Bl,
                      const float* __restrict__ bias, const float* __restrict__ res,
                      float* __restrict__ C,
                      unsigned short* __restrict__ Ch, unsigned short* __restrict__ Cl,
                      int M, int N, int K)
{
    extern __shared__ __align__(16) char smem[];
    uint32_t sb = smem_u32(smem);

    int tid = threadIdx.x;
    int lane = tid & 31, wid = tid >> 5;
    int wm = wid >> 1, wn = wid & 1;
    int bn = blockIdx.x, bm = blockIdx.y;

    int r0 = tid >> 2, c0 = tid & 3;
    uint32_t so = (uint32_t)(r0 * 80 + c0 * 16);
    size_t goff = (size_t)r0 * K + c0 * 8;
    const unsigned short* pA0 = Ah + (size_t)(bm * 128) * K + goff;
    const unsigned short* pL0 = Al + (size_t)(bm * 128) * K + goff;
    const unsigned short* pB0 = Bh + (size_t)(bn * 128) * K + goff;
    const unsigned short* pX0 = Bl + (size_t)(bn * 128) * K + goff;
    size_t half = (size_t)64 * K;

    uint32_t rpA = (uint32_t)((wm * 32 + (lane & 15)) * 80 + (lane >> 4) * 16);
    int g = lane >> 3, l8 = lane & 7;
    uint32_t rpB = (uint32_t)((wn * 64 + l8 + (g >> 1) * 8) * 80 + (g & 1) * 16);

    float acc[2][8][4];
    #pragma unroll
    for (int mt = 0; mt < 2; mt++)
        #pragma unroll
        for (int nt = 0; nt < 8; nt++)
            #pragma unroll
            for (int i = 0; i < 4; i++) acc[mt][nt][i] = 0.f;

    int nch = K >> 5;

    #define GB_ISSUE(kc) do {                                            \
        if ((kc) < nch) {                                                \
            uint32_t sa = sb + (uint32_t)((kc) & 1) * GB_STAGE;          \
            int off = (kc) * 32;                                         \
            CPA16(sa + so,                        pA0 + off);            \
            CPA16(sa + so + 5120,                 pA0 + half + off);     \
            CPA16(sa + GB_TILE + so,              pL0 + off);            \
            CPA16(sa + GB_TILE + so + 5120,       pL0 + half + off);     \
            CPA16(sa + 2*GB_TILE + so,            pB0 + off);            \
            CPA16(sa + 2*GB_TILE + so + 5120,     pB0 + half + off);     \
            CPA16(sa + 3*GB_TILE + so,            pX0 + off);            \
            CPA16(sa + 3*GB_TILE + so + 5120,     pX0 + half + off);     \
        }                                                                \
        CPC();                                                           \
    } while (0)

    GB_ISSUE(0);
    GB_ISSUE(1);

    for (int kc = 0; kc < nch; kc++) {
        CPW(1);
        __syncthreads();

        uint32_t base = sb + (uint32_t)(kc & 1) * GB_STAGE;
        uint32_t aHi = base, aLo = base + GB_TILE;
        uint32_t bHi = base + 2*GB_TILE, bLo = base + 3*GB_TILE;

        #pragma unroll
        for (int k16 = 0; k16 < 2; k16++) {
            uint32_t ko = (uint32_t)k16 * 32;
            uint32_t ah[8], ax[8], bb[16];

            ldsm4(ah + 0, aHi + rpA + ko);
            ldsm4(ah + 4, aHi + rpA + 1280 + ko);
            ldsm4(ax + 0, aLo + rpA + ko);
            ldsm4(ax + 4, aLo + rpA + 1280 + ko);
            #pragma unroll
            for (int i = 0; i < 4; i++)
                ldsm4(bb + i*4, bHi + rpB + (uint32_t)i*1280 + ko);
            #pragma unroll
            for (int mt = 0; mt < 2; mt++)
                #pragma unroll
                for (int nt = 0; nt < 8; nt++)
                    mma16816(acc[mt][nt], ah + mt*4, bb + nt*2);
            #pragma unroll
            for (int mt = 0; mt < 2; mt++)
                #pragma unroll
                for (int nt = 0; nt < 8; nt++)
                    mma16816(acc[mt][nt], ax + mt*4, bb + nt*2);
            #pragma unroll
            for (int i = 0; i < 4; i++)
                ldsm4(bb + i*4, bLo + rpB + (uint32_t)i*1280 + ko);
            #pragma unroll
            for (int mt = 0; mt < 2; mt++)
                #pragma unroll
                for (int nt = 0; nt < 8; nt++)
                    mma16816(acc[mt][nt], ah + mt*4, bb + nt*2);
        }

        __syncthreads();
        GB_ISSUE(kc + 2);
    }
    #undef GB_ISSUE

    #pragma unroll
    for (int mt = 0; mt < 2; mt++) {
        int gr0 = bm*128 + wm*32 + mt*16 + (lane >> 2);
        #pragma unroll
        for (int nt = 0; nt < 8; nt++) {
            int gc = bn*128 + wn*64 + nt*8 + (lane & 3)*2;
            #pragma unroll
            for (int hfl = 0; hfl < 2; hfl++) {
                int row = gr0 + hfl*8;
                float v0 = acc[mt][nt][hfl*2+0];
                float v1 = acc[mt][nt][hfl*2+1];
                if (FLAGS & F_BIAS) {
                    v0 += __ldg(bias + gc);
                    v1 += __ldg(bias + gc + 1);
                }
                if (FLAGS & F_RES) {
                    float2 rr = *(const float2*)(res + (size_t)row * N + gc);
                    v0 += rr.x; v1 += rr.y;
                }
                if (FLAGS & F_RELU) { v0 = fmaxf(v0, 0.f); v1 = fmaxf(v1, 0.f); }
                if (FLAGS & F_OUTBF) {
                    uint32_t h, l;
                    packhl(v0, v1, h, l);
                    *(uint32_t*)(Ch + (size_t)row * N + gc) = h;
                    *(uint32_t*)(Cl + (size_t)row * N + gc) = l;
                } else {
                    float2 o = make_float2(v0, v1);
                    *(float2*)(C + (size_t)row * N + gc) = o;
                }
            }
        }
    }
}

// ================= Flash attention: bf16 hi/lo in, cp.async 3-stage =================
// Q tile 128, K/V tiles 64, 8 warps. Stage = Khi|Klo|Vhi|Vlo, 64 rows x 144 B each.
#define FST_TIL  9216                 // 64*144
#define FST_STG  (4 * FST_TIL)        // 36864
#define FST_SMEM (3 * FST_STG)        // 110592

__global__ __launch_bounds__(256, 1)
void flash_mma_kernel(const unsigned short* __restrict__ qh_g,
                      const unsigned short* __restrict__ ql_g,
                      unsigned short* __restrict__ oh,
                      unsigned short* __restrict__ ol)
{
    extern __shared__ __align__(16) char smf[];
    uint32_t sb  = smem_u32(smf);

    int tid = threadIdx.x, lane = tid & 31, wid = tid >> 5;
    int qi = blockIdx.x, bh = blockIdx.y;
    int b = bh >> 4, h = bh & 15;

    const int QKV_W = 3 * E_DIM;   // 3072
    size_t rowbase = (size_t)b * S_DIM;

    // ---- stage Q (hi/lo) through stage-0 smem, build register fragments ----
    {
        int r = tid >> 1, ce = (tid & 1) * 32;        // 32-elem (64B) half-row
        const unsigned short* sh = qh_g + (rowbase + qi*128 + r) * QKV_W + h*64 + ce;
        const unsigned short* sl = ql_g + (rowbase + qi*128 + r) * QKV_W + h*64 + ce;
        uint32_t d = sb + (uint32_t)(r*144 + ce*2);
        #pragma unroll
        for (int k = 0; k < 4; k++) {
            CPA16(d + k*16,         sh + k*8);
            CPA16(d + 18432 + k*16, sl + k*8);
        }
        CPC(); CPW(0);
    }
    __syncthreads();

    uint32_t qh[4][4], ql[4][4];
    {
        uint32_t ra = sb + (uint32_t)((wid*16 + (lane & 15))*144 + (lane >> 4)*16);
        #pragma unroll
        for (int ks = 0; ks < 4; ks++) {
            ldsm4(qh[ks], ra + ks*32);
            ldsm4(ql[ks], ra + 18432 + ks*32);
        }
    }
    __syncthreads();   // Q staging done before pipeline overwrites stage 0

    float oacc[8][4];
    #pragma unroll
    for (int nt = 0; nt < 8; nt++)
        #pragma unroll
        for (int i = 0; i < 4; i++) oacc[nt][i] = 0.f;
    float rm0 = -1e30f, rm1 = -1e30f, rl0 = 0.f, rl1 = 0.f;

    int g = lane >> 3, l8 = lane & 7;
    uint32_t rpB = (uint32_t)((l8 + (g >> 1)*8)*144 + (g & 1)*16);
    uint32_t rpV = (uint32_t)((lane & 15)*144 + (lane >> 4)*16);

    int rowlim = qi*128 + wid*16 + 15;
    int nj = 2*qi + 2;

    // K/V cp.async mapping: r=tid>>2 (0..63), c=tid&3 -> 32B chunk pair
    int rkv = tid >> 2, ckv = tid & 3;
    uint32_t skv = (uint32_t)(rkv*144 + ckv*32);
    const unsigned short* kh0 = qh_g + (rowbase + rkv) * QKV_W + E_DIM   + h*64 + ckv*16;
    const unsigned short* kl0 = ql_g + (rowbase + rkv) * QKV_W + E_DIM   + h*64 + ckv*16;
    const unsigned short* vh0 = qh_g + (rowbase + rkv) * QKV_W + 2*E_DIM + h*64 + ckv*16;
    const unsigned short* vl0 = ql_g + (rowbase + rkv) * QKV_W + 2*E_DIM + h*64 + ckv*16;

    #define FS_ISSUE(jt) do {                                              \
        if ((jt) < nj) {                                                   \
            uint32_t sg = sb + (uint32_t)((jt) % 3) * FST_STG;             \
            size_t off = (size_t)(jt) * 64 * QKV_W;                        \
            CPA16(sg + skv,                  kh0 + off);                   \
            CPA16(sg + skv + 16,             kh0 + off + 8);               \
            CPA16(sg + FST_TIL + skv,        kl0 + off);                   \
            CPA16(sg + FST_TIL + skv + 16,   kl0 + off + 8);               \
            CPA16(sg + 2*FST_TIL + skv,      vh0 + off);                   \
            CPA16(sg + 2*FST_TIL + skv + 16, vh0 + off + 8);               \
            CPA16(sg + 3*FST_TIL + skv,      vl0 + off);                   \
            CPA16(sg + 3*FST_TIL + skv + 16, vl0 + off + 8);               \
        }                                                                  \
        CPC();                                                             \
    } while (0)

    FS_ISSUE(0);
    FS_ISSUE(1);

    for (int jt = 0; jt < nj; jt++) {
        CPW(1);
        __syncthreads();     // stage jt visible; stage jt-1 readers all done
        FS_ISSUE(jt + 2);    // prefetch overlaps compute below

        if (jt*64 > rowlim) continue;

        uint32_t Khi = sb + (uint32_t)(jt % 3) * FST_STG;
        uint32_t Klo = Khi + FST_TIL;
        uint32_t Vhi = Khi + 2*FST_TIL;
        uint32_t Vlo = Khi + 3*FST_TIL;

        // ---- S = Q K^T (3 bf16 products), then scale by 1/8 ----
        float s[8][4];
        #pragma unroll
        for (int nt = 0; nt < 8; nt++)
            #pragma unroll
            for (int i = 0; i < 4; i++) s[nt][i] = 0.f;
        {
            uint32_t kb[16];
            #pragma unroll
            for (int ks = 0; ks < 4; ks++) {
                #pragma unroll
                for (int i = 0; i < 4; i++)
                    ldsm4(kb + 4*i, Khi + rpB + (uint32_t)i*2304 + ks*32);
                #pragma unroll
                for (int nt = 0; nt < 8; nt++)
                    mma16816(s[nt], qh[ks], kb + 2*nt);
                #pragma unroll
                for (int nt = 0; nt < 8; nt++)
                    mma16816(s[nt], ql[ks], kb + 2*nt);
                #pragma unroll
                for (int i = 0; i < 4; i++)
                    ldsm4(kb + 4*i, Klo + rpB + (uint32_t)i*2304 + ks*32);
                #pragma unroll
                for (int nt = 0; nt < 8; nt++)
                    mma16816(s[nt], qh[ks], kb + 2*nt);
            }
        }
        #pragma unroll
        for (int nt = 0; nt < 8; nt++)
            #pragma unroll
            for (int i = 0; i < 4; i++) s[nt][i] *= 0.125f;

        int row0 = qi*128 + wid*16 + (lane >> 2);
        if (jt >= 2*qi) {
            #pragma unroll
            for (int nt = 0; nt < 8; nt++) {
                int col = jt*64 + nt*8 + (lane & 3)*2;
                if (col     > row0)     s[nt][0] = -1e30f;
                if (col + 1 > row0)     s[nt][1] = -1e30f;
                if (col     > row0 + 8) s[nt][2] = -1e30f;
                if (col + 1 > row0 + 8) s[nt][3] = -1e30f;
            }
        }

        float m0 = -1e30f, m1 = -1e30f;
        #pragma unroll
        for (int nt = 0; nt < 8; nt++) {
            m0 = fmaxf(m0, fmaxf(s[nt][0], s[nt][1]));
            m1 = fmaxf(m1, fmaxf(s[nt][2], s[nt][3]));
        }
        m0 = fmaxf(m0, __shfl_xor_sync(0xffffffffu, m0, 1));
        m0 = fmaxf(m0, __shfl_xor_sync(0xffffffffu, m0, 2));
        m1 = fmaxf(m1, __shfl_xor_sync(0xffffffffu, m1, 1));
        m1 = fmaxf(m1, __shfl_xor_sync(0xffffffffu, m1, 2));

        float mn0 = fmaxf(rm0, m0), mn1 = fmaxf(rm1, m1);
        float al0 = __expf(rm0 - mn0), al1 = __expf(rm1 - mn1);
        rm0 = mn0; rm1 = mn1;

        float sum0 = 0.f, sum1 = 0.f;
        #pragma unroll
        for (int nt = 0; nt < 8; nt++) {
            s[nt][0] = __expf(s[nt][0] - mn0);
            s[nt][1] = __expf(s[nt][1] - mn0);
            s[nt][2] = __expf(s[nt][2] - mn1);
            s[nt][3] = __expf(s[nt][3] - mn1);
            sum0 += s[nt][0] + s[nt][1];
            sum1 += s[nt][2] + s[nt][3];
        }
        sum0 += __shfl_xor_sync(0xffffffffu, sum0, 1);
        sum0 += __shfl_xor_sync(0xffffffffu, sum0, 2);
        sum1 += __shfl_xor_sync(0xffffffffu, sum1, 1);
        sum1 += __shfl_xor_sync(0xffffffffu, sum1, 2);
        rl0 = rl0 * al0 + sum0;
        rl1 = rl1 * al1 + sum1;

        #pragma unroll
        for (int nt = 0; nt < 8; nt++) {
            oacc[nt][0] *= al0; oacc[nt][1] *= al0;
            oacc[nt][2] *= al1; oacc[nt][3] *= al1;
        }

        uint32_t ph[4][4], pl[4][4];
        #pragma unroll
        for (int ks = 0; ks < 4; ks++) {
            int j0 = 2*ks, j1 = 2*ks + 1;
            packhl(s[j0][0], s[j0][1], ph[ks][0], pl[ks][0]);
            packhl(s[j0][2], s[j0][3], ph[ks][1], pl[ks][1]);
            packhl(s[j1][0], s[j1][1], ph[ks][2], pl[ks][2]);
            packhl(s[j1][2], s[j1][3], ph[ks][3], pl[ks][3]);
        }

        {
            uint32_t vb[16];
            #pragma unroll
            for (int ks = 0; ks < 4; ks++) {
                #pragma unroll
                for (int i = 0; i < 4; i++)
                    ldsm4t(vb + 4*i, Vhi + rpV + (uint32_t)ks*2304 + (uint32_t)i*32);
                #pragma unroll
                for (int nt = 0; nt < 8; nt++)
                    mma16816(oacc[nt], ph[ks], vb + 2*nt);
                #pragma unroll
                for (int nt = 0; nt < 8; nt++)
                    mma16816(oacc[nt], pl[ks], vb + 2*nt);
                #pragma unroll
                for (int i = 0; i < 4; i++)
                    ldsm4t(vb + 4*i, Vlo + rpV + (uint32_t)ks*2304 + (uint32_t)i*32);
                #pragma unroll
                for (int nt = 0; nt < 8; nt++)
                    mma16816(oacc[nt], ph[ks], vb + 2*nt);
            }
        }
    }
    #undef FS_ISSUE

    // ---- epilogue: normalize, write bf16 hi/lo ----
    float inv0 = 1.0f / rl0, inv1 = 1.0f / rl1;
    int row0 = qi*128 + wid*16 + (lane >> 2);
    size_t obase = (size_t)b * S_DIM * E_DIM + h * 64;
    #pragma unroll
    for (int nt = 0; nt < 8; nt++) {
        int col = nt*8 + (lane & 3)*2;
        uint32_t h0, l0, h1, l1;
        packhl(oacc[nt][0]*inv0, oacc[nt][1]*inv0, h0, l0);
        packhl(oacc[nt][2]*inv1, oacc[nt][3]*inv1, h1, l1);
        *(uint32_t*)(oh + obase + (size_t)row0       * E_DIM + col) = h0;
        *(uint32_t*)(ol + obase + (size_t)row0       * E_DIM + col) = l0;
        *(uint32_t*)(oh + obase + (size_t)(row0 + 8) * E_DIM + col) = h1;
        *(uint32_t*)(ol + obase + (size_t)(row0 + 8) * E_DIM + col) = l1;
    }
}

// ---------------- launch ----------------
extern "C" void kernel_launch(void* const* d_in, const int* in_sizes, int n_in,
                              void* d_out, int out_size)
{
    const float* x      = (const float*)d_in[0];
    const float* w_in   = (const float*)d_in[1];
    const float* w_out  = (const float*)d_in[2];
    const float* w_fc   = (const float*)d_in[3];
    const float* b_fc   = (const float*)d_in[4];
    const float* w_proj = (const float*)d_in[5];
    const float* b_proj = (const float*)d_in[6];
    float* out = (float*)d_out;

    void *px2, *phh, *phl, *pqh, *pql, *poh, *pol, *pmh, *pml;
    void *pwinh, *pwinl, *pwouth, *pwoutl, *pwfch, *pwfcl, *pwprh, *pwprl;
    cudaGetSymbolAddress(&px2,  g_x2);
    cudaGetSymbolAddress(&phh,  g_hh);   cudaGetSymbolAddress(&phl,  g_hl);
    cudaGetSymbolAddress(&pqh,  g_qkvh); cudaGetSymbolAddress(&pql,  g_qkvl);
    cudaGetSymbolAddress(&poh,  g_oh);   cudaGetSymbolAddress(&pol,  g_ol);
    cudaGetSymbolAddress(&pmh,  g_mh);   cudaGetSymbolAddress(&pml,  g_ml);
    cudaGetSymbolAddress(&pwinh,  g_winh);  cudaGetSymbolAddress(&pwinl,  g_winl);
    cudaGetSymbolAddress(&pwouth, g_wouth); cudaGetSymbolAddress(&pwoutl, g_woutl);
    cudaGetSymbolAddress(&pwfch,  g_wfch);  cudaGetSymbolAddress(&pwfcl,  g_wfcl);
    cudaGetSymbolAddress(&pwprh,  g_wprh);  cudaGetSymbolAddress(&pwprl,  g_wprl);

    float* bx2  = (float*)px2;
    unsigned short *bhh = (unsigned short*)phh, *bhl = (unsigned short*)phl;
    unsigned short *bqh = (unsigned short*)pqh, *bql = (unsigned short*)pql;
    unsigned short *boh = (unsigned short*)poh, *bol = (unsigned short*)pol;
    unsigned short *bmh = (unsigned short*)pmh, *bml = (unsigned short*)pml;
    unsigned short *winh = (unsigned short*)pwinh, *winl = (unsigned short*)pwinl;
    unsigned short *wouth = (unsigned short*)pwouth, *woutl = (unsigned short*)pwoutl;
    unsigned short *wfch = (unsigned short*)pwfch, *wfcl = (unsigned short*)pwfcl;
    unsigned short *wprh = (unsigned short*)pwprh, *wprl = (unsigned short*)pwprl;

    cudaFuncSetAttribute(flash_mma_kernel,
                         cudaFuncAttributeMaxDynamicSharedMemorySize, FST_SMEM);
    cudaFuncSetAttribute(gemm_bf16_kernel<F_OUTBF>,
                         cudaFuncAttributeMaxDynamicSharedMemorySize, GB_SMEM);
    cudaFuncSetAttribute(gemm_bf16_kernel<F_RES>,
                         cudaFuncAttributeMaxDynamicSharedMemorySize, GB_SMEM);
    cudaFuncSetAttribute(gemm_bf16_kernel<F_BIAS|F_RELU|F_OUTBF>,
                         cudaFuncAttributeMaxDynamicSharedMemorySize, GB_SMEM);
    cudaFuncSetAttribute(gemm_bf16_kernel<F_BIAS|F_RES>,
                         cudaFuncAttributeMaxDynamicSharedMemorySize, GB_SMEM);

    // 0) weight conversions
    cvtw_kernel<<<1024, 256>>>(w_in,   winh,  winl,  3*E_DIM*E_DIM/8);
    cvtw_kernel<<<1024, 256>>>(w_out,  wouth, woutl, E_DIM*E_DIM/8);
    cvtw_kernel<<<1024, 256>>>(w_fc,   wfch,  wfcl,  4*E_DIM*E_DIM/8);
    cvtw_kernel<<<1024, 256>>>(w_proj, wprh,  wprl,  4*E_DIM*E_DIM/8);

    // 1) h = LN(x) -> bf16 hi/lo
    ln_kernel<<<NROWS, 256>>>(x, bhh, bhl);
    // 2) qkv = h @ w_in^T -> bf16 hi/lo
    gemm_bf16_kernel<F_OUTBF><<<dim3(3072/128, NROWS/128), 256, GB_SMEM>>>(
        bhh, bhl, winh, winl, nullptr, nullptr, nullptr, bqh, bql,
        NROWS, 3072, 1024);
    // 3) o = causal attention(qkv) -> bf16 hi/lo
    flash_mma_kernel<<<dim3(S_DIM/128, B_DIM*H_DIM), 256, FST_SMEM>>>(
        bqh, bql, boh, bol);
    // 4) x2 = o @ w_out^T + x   (fp32)
    gemm_bf16_kernel<F_RES><<<dim3(1024/128, NROWS/128), 256, GB_SMEM>>>(
        boh, bol, wouth, woutl, nullptr, x, bx2, nullptr, nullptr,
        NROWS, 1024, 1024);
    // 5) h2 = LN(x2) -> bf16 hi/lo
    ln_kernel<<<NROWS, 256>>>(bx2, bhh, bhl);
    // 6) m = relu(h2 @ w_fc^T + b_fc) -> bf16 hi/lo
    gemm_bf16_kernel<F_BIAS|F_RELU|F_OUTBF><<<dim3(4096/128, NROWS/128), 256, GB_SMEM>>>(
        bhh, bhl, wfch, wfcl, b_fc, nullptr, nullptr, bmh, bml,
        NROWS, 4096, 1024);
    // 7) out = m @ w_proj^T + b_proj + x2   (fp32)
    gemm_bf16_kernel<F_BIAS|F_RES><<<dim3(1024/128, NROWS/128), 256, GB_SMEM>>>(
        bmh, bml, wprh, wprl, b_proj, bx2, out, nullptr, nullptr,
        NROWS, 1024, 4096);
}